// round 4
// baseline (speedup 1.0000x reference)
#include <cuda_runtime.h>
#include <math.h>
#include <float.h>

#define Bsz 4
#define Npt 4096
#define KNN 20
#define EPSBN 1e-5f
#define PARTS 4
#define NROWS (Bsz * Npt)

// ---------------- scratch (device globals; no allocations) ----------------
__device__ float d_xcat[Bsz * 192 * Npt];           // x1|x2|x3 concatenated
__device__ float d_AC[Bsz * 128 * Npt];             // A (0:64) | Cc (64:128)
__device__ float d_y5[Bsz * 512 * Npt];
__device__ float d_y4[Bsz * 512 * Npt];
__device__ float d_y6[Bsz * 256 * Npt];
__device__ float d_y7[Bsz * 128 * Npt];
__device__ float d_sq[Bsz * Npt];
__device__ int   d_idx[Bsz * Npt * KNN];
__device__ float d_gmax[Bsz * 512];
__device__ float d_bias5[Bsz * 512];
__device__ float d_Wc2[128 * 64], d_Wc3[128 * 64];
__device__ float d_ptv[PARTS * KNN * NROWS];
__device__ int   d_pti[PARTS * KNN * NROWS];
__device__ float d_mean[64];
__device__ float d_rstd[64];

__device__ __forceinline__ float lrelu(float v) { return v >= 0.f ? v : 0.2f * v; }

// ---------------- conv1: 3 -> 64 ----------------
__global__ void k_conv1(const float* __restrict__ x, const float* __restrict__ W1) {
    int n = blockIdx.x * 256 + threadIdx.x;
    int o = blockIdx.y, b = blockIdx.z;
    float v = W1[o * 3 + 0] * x[(b * 3 + 0) * Npt + n]
            + W1[o * 3 + 1] * x[(b * 3 + 1) * Npt + n]
            + W1[o * 3 + 2] * x[(b * 3 + 2) * Npt + n];
    d_xcat[((long)b * 192 + o) * Npt + n] = v;
}

// ---------------- fused BN stats + apply + lrelu (in place) ----------------
__global__ void k_statsapply(float* __restrict__ buf, int CT, int c0,
                             const float* __restrict__ gamma, const float* __restrict__ beta) {
    int o = blockIdx.x;
    double s = 0.0, s2 = 0.0;
    for (int i = threadIdx.x; i < Bsz * Npt; i += 256) {
        int b = i >> 12, n = i & (Npt - 1);
        float v = buf[((long)b * CT + c0 + o) * Npt + n];
        s += v; s2 += (double)v * (double)v;
    }
    __shared__ double sh[256], sh2[256];
    __shared__ float smv, srv;
    sh[threadIdx.x] = s; sh2[threadIdx.x] = s2; __syncthreads();
    for (int st = 128; st > 0; st >>= 1) {
        if (threadIdx.x < st) { sh[threadIdx.x] += sh[threadIdx.x + st]; sh2[threadIdx.x] += sh2[threadIdx.x + st]; }
        __syncthreads();
    }
    if (threadIdx.x == 0) {
        double cnt = (double)(Bsz * Npt);
        double m = sh[0] / cnt;
        double var = sh2[0] / cnt - m * m;
        smv = (float)m;
        srv = rsqrtf((float)fmax(var, 0.0) + EPSBN);
    }
    __syncthreads();
    float m = smv, r = srv, g = gamma[o], be = beta[o];
    for (int i = threadIdx.x; i < Bsz * Npt; i += 256) {
        int b = i >> 12, n = i & (Npt - 1);
        long off = ((long)b * CT + c0 + o) * Npt + n;
        buf[off] = lrelu((buf[off] - m) * r * g + be);
    }
}

// ---------------- squared norms ----------------
__global__ void k_sqnorm(int c0) {
    int n = blockIdx.x * 256 + threadIdx.x, b = blockIdx.y;
    float s = 0.f;
    #pragma unroll 8
    for (int c = 0; c < 64; c++) {
        float v = d_xcat[((long)b * 192 + c0 + c) * Npt + n];
        s += v * v;
    }
    d_sq[b * Npt + n] = s;
}

// ======== fused distance GEMM + partial top-20 ========
// block: 128 q-rows x 1024 columns (8 tiles of 128). Q strip resident in smem.
// topk value = 2*dot - sq[n] (row-constant sq[q] dropped: order-preserving).
#define TLS 132
__global__ void __launch_bounds__(256, 1) k_dist_topk(int c0) {
    extern __shared__ float smem[];
    float* Qs = smem;                   // [64][132] k-major
    float* Ms = Qs + 64 * 132;          // [64][128] k-major
    float* Tl = Ms + 64 * 128;          // [128][TLS]
    int cs = blockIdx.x, qs = blockIdx.y, b = blockIdx.z;
    int q0 = qs * 128, nbase = cs * 1024;
    int tid = threadIdx.x, tx = tid & 15, ty = tid >> 4;
    const float* xb = d_xcat + ((long)b * 192 + c0) * Npt;
    // resident Q strip
    for (int i = tid; i < 64 * 128; i += 256) {
        int k = i >> 7, r = i & 127;
        Qs[k * 132 + r] = xb[(long)k * Npt + q0 + r];
    }
    float topv[20]; int topi[20];
    #pragma unroll
    for (int t = 0; t < 20; t++) { topv[t] = -FLT_MAX; topi[t] = nbase; }
    float curmin = -FLT_MAX; int minpos = 0;

    for (int t = 0; t < 8; t++) {
        int n0 = nbase + t * 128;
        __syncthreads();
        for (int i = tid; i < 64 * 128; i += 256) {
            int k = i >> 7, c = i & 127;
            Ms[k * 128 + c] = xb[(long)k * Npt + n0 + c];
        }
        __syncthreads();
        float acc[2][2][4][4] = {};
        #pragma unroll 8
        for (int k = 0; k < 64; k++) {
            float4 a0 = *(const float4*)&Qs[k * 132 + ty * 4];
            float4 a1 = *(const float4*)&Qs[k * 132 + 64 + ty * 4];
            float4 b0 = *(const float4*)&Ms[k * 128 + tx * 4];
            float4 b1 = *(const float4*)&Ms[k * 128 + 64 + tx * 4];
            float aa[2][4] = {{a0.x, a0.y, a0.z, a0.w}, {a1.x, a1.y, a1.z, a1.w}};
            float bb[2][4] = {{b0.x, b0.y, b0.z, b0.w}, {b1.x, b1.y, b1.z, b1.w}};
            #pragma unroll
            for (int ii = 0; ii < 2; ii++)
                #pragma unroll
                for (int i = 0; i < 4; i++)
                    #pragma unroll
                    for (int jj = 0; jj < 2; jj++)
                        #pragma unroll
                        for (int j = 0; j < 4; j++)
                            acc[ii][jj][i][j] += aa[ii][i] * bb[jj][j];
        }
        long bN = (long)b * Npt;
        float4 s0 = *(const float4*)&d_sq[bN + n0 + tx * 4];
        float4 s1 = *(const float4*)&d_sq[bN + n0 + 64 + tx * 4];
        float sn0[4] = {s0.x, s0.y, s0.z, s0.w};
        float sn1[4] = {s1.x, s1.y, s1.z, s1.w};
        #pragma unroll
        for (int ii = 0; ii < 2; ii++)
            #pragma unroll
            for (int i = 0; i < 4; i++) {
                int row = ii * 64 + ty * 4 + i;
                #pragma unroll
                for (int j = 0; j < 4; j++) {
                    Tl[row * TLS + tx * 4 + j]      = 2.f * acc[ii][0][i][j] - sn0[j];
                    Tl[row * TLS + 64 + tx * 4 + j] = 2.f * acc[ii][1][i][j] - sn1[j];
                }
            }
        __syncthreads();
        if (tid < 128) {
            #pragma unroll 4
            for (int j = 0; j < 128; j++) {
                float v = Tl[tid * TLS + j];
                if (v > curmin) {
                    topv[minpos] = v; topi[minpos] = n0 + j;
                    curmin = topv[0]; minpos = 0;
                    #pragma unroll
                    for (int u = 1; u < 20; u++)
                        if (topv[u] < curmin) { curmin = topv[u]; minpos = u; }
                }
            }
        }
    }
    if (tid < 128) {
        int row = b * Npt + q0 + tid;
        #pragma unroll
        for (int t = 0; t < 20; t++) {
            d_ptv[(cs * 20 + t) * NROWS + row] = topv[t];
            d_pti[(cs * 20 + t) * NROWS + row] = topi[t];
        }
    }
}
#define DTK_SMEM ((64 * 132 + 64 * 128 + 128 * TLS) * 4)

// ---------------- merge 4 partial top-20 lists (ascending part order keeps ties) ----------------
__global__ void k_topk_merge() {
    int row = blockIdx.x * 256 + threadIdx.x;
    float topv[20]; int topi[20];
    #pragma unroll
    for (int t = 0; t < 20; t++) { topv[t] = -FLT_MAX; topi[t] = 0; }
    float curmin = -FLT_MAX; int minpos = 0;
    for (int p = 0; p < PARTS; p++) {
        #pragma unroll
        for (int t = 0; t < 20; t++) {
            float v = d_ptv[(p * 20 + t) * NROWS + row];
            int ix = d_pti[(p * 20 + t) * NROWS + row];
            if (v > curmin) {
                topv[minpos] = v; topi[minpos] = ix;
                curmin = topv[0]; minpos = 0;
                #pragma unroll
                for (int u = 1; u < 20; u++)
                    if (topv[u] < curmin) { curmin = topv[u]; minpos = u; }
            }
        }
    }
    #pragma unroll
    for (int t = 0; t < 20; t++) d_idx[row * KNN + t] = topi[t];
}

// ---------------- combined weight prep: rows 0:64 = W[:, :64], rows 64:128 = W[:,64:] - W[:, :64] ----------------
__global__ void k_prepw(const float* __restrict__ W, float* __restrict__ Wc) {
    int o = blockIdx.x, c = threadIdx.x;
    float a = W[o * 128 + c], bb = W[o * 128 + 64 + c];
    Wc[o * 64 + c] = a;
    Wc[(64 + o) * 64 + c] = bb - a;
}

// ======== 128x128 tile feature GEMM ========
__global__ void __launch_bounds__(256, 1) k_gemm128(
        float* __restrict__ out, const float* __restrict__ in,
        const float* __restrict__ W, const float* __restrict__ biasBO,
        int C, int ldw, int CTin, int c0in, int CTout, int c0out) {
    __shared__ float Ws[16][132];
    __shared__ float Xs[16][128];
    int b = blockIdx.z, o0 = blockIdx.y * 128, n0 = blockIdx.x * 128;
    int tid = threadIdx.x, tx = tid & 15, ty = tid >> 4;
    float acc[2][2][4][4] = {};
    const float* inB = in + ((long)b * CTin + c0in) * Npt + n0;
    #pragma unroll 1
    for (int ck = 0; ck < C; ck += 16) {
        #pragma unroll
        for (int r = 0; r < 8; r++) {
            int idx = r * 256 + tid;
            int oo = idx >> 4, cc = idx & 15;
            Ws[cc][oo] = W[(long)(o0 + oo) * ldw + ck + cc];
        }
        #pragma unroll
        for (int r = 0; r < 8; r++) {
            int idx = r * 256 + tid;
            int cc = idx >> 7, e = idx & 127;
            Xs[cc][e] = inB[(long)(ck + cc) * Npt + e];
        }
        __syncthreads();
        #pragma unroll
        for (int k = 0; k < 16; k++) {
            float4 a0 = *(const float4*)&Ws[k][ty * 4];
            float4 a1 = *(const float4*)&Ws[k][64 + ty * 4];
            float4 b0 = *(const float4*)&Xs[k][tx * 4];
            float4 b1 = *(const float4*)&Xs[k][64 + tx * 4];
            float aa[2][4] = {{a0.x, a0.y, a0.z, a0.w}, {a1.x, a1.y, a1.z, a1.w}};
            float bb[2][4] = {{b0.x, b0.y, b0.z, b0.w}, {b1.x, b1.y, b1.z, b1.w}};
            #pragma unroll
            for (int ii = 0; ii < 2; ii++)
                #pragma unroll
                for (int i = 0; i < 4; i++)
                    #pragma unroll
                    for (int jj = 0; jj < 2; jj++)
                        #pragma unroll
                        for (int j = 0; j < 4; j++)
                            acc[ii][jj][i][j] += aa[ii][i] * bb[jj][j];
        }
        __syncthreads();
    }
    #pragma unroll
    for (int ii = 0; ii < 2; ii++) {
        #pragma unroll
        for (int i = 0; i < 4; i++) {
            int o = o0 + ii * 64 + ty * 4 + i;
            float bias = biasBO ? biasBO[b * 512 + o] : 0.f;
            float* row = out + ((long)b * CTout + c0out + o) * Npt + n0;
            float4 v0, v1;
            v0.x = acc[ii][0][i][0] + bias; v0.y = acc[ii][0][i][1] + bias;
            v0.z = acc[ii][0][i][2] + bias; v0.w = acc[ii][0][i][3] + bias;
            v1.x = acc[ii][1][i][0] + bias; v1.y = acc[ii][1][i][1] + bias;
            v1.z = acc[ii][1][i][2] + bias; v1.w = acc[ii][1][i][3] + bias;
            *(float4*)&row[tx * 4] = v0;
            *(float4*)&row[64 + tx * 4] = v1;
        }
    }
}

// ---------------- edge-conv BN stats over (b, n, k) ----------------
__global__ void k_edge_stats() {
    int o = blockIdx.x;
    double s = 0.0, s2 = 0.0;
    const int TOT = Bsz * Npt * KNN;
    for (int i = threadIdx.x; i < TOT; i += 256) {
        int b = i / (Npt * KNN);
        int rem = i - b * (Npt * KNN);
        int n = rem / KNN;
        int j = d_idx[i];
        float v = d_AC[((long)b * 128 + o) * Npt + j] + d_AC[((long)b * 128 + 64 + o) * Npt + n];
        s += v; s2 += (double)v * (double)v;
    }
    __shared__ double sh[256], sh2[256];
    sh[threadIdx.x] = s; sh2[threadIdx.x] = s2; __syncthreads();
    for (int st = 128; st > 0; st >>= 1) {
        if (threadIdx.x < st) { sh[threadIdx.x] += sh[threadIdx.x + st]; sh2[threadIdx.x] += sh2[threadIdx.x + st]; }
        __syncthreads();
    }
    if (threadIdx.x == 0) {
        double cnt = (double)TOT;
        double m = sh[0] / cnt;
        double var = sh2[0] / cnt - m * m;
        d_mean[o] = (float)m;
        d_rstd[o] = rsqrtf((float)fmax(var, 0.0) + EPSBN);
    }
}

// ---------------- edge-conv BN+lrelu+max_k ----------------
__global__ void k_edge_apply(const float* __restrict__ gamma, const float* __restrict__ beta, int c0out) {
    int n = blockIdx.x * 256 + threadIdx.x, o = blockIdx.y, b = blockIdx.z;
    float m = d_mean[o], r = d_rstd[o], g = gamma[o], be = beta[o];
    const float* Ab = d_AC + ((long)b * 128 + o) * Npt;
    float cc = d_AC[((long)b * 128 + 64 + o) * Npt + n];
    const int* ip = d_idx + (b * Npt + n) * KNN;
    float best = -FLT_MAX;
    #pragma unroll 4
    for (int k = 0; k < KNN; k++) {
        float v = Ab[ip[k]] + cc;
        v = lrelu((v - m) * r * g + be);
        best = fmaxf(best, v);
    }
    d_xcat[((long)b * 192 + c0out + o) * Npt + n] = best;
}

// ---------------- fused stats + BN + lrelu + max over n -> gmax ----------------
__global__ void k_stats_gmax(const float* __restrict__ buf,
                             const float* __restrict__ gamma, const float* __restrict__ beta) {
    int o = blockIdx.x;  // 512
    double s = 0.0, s2 = 0.0;
    for (int i = threadIdx.x; i < Bsz * Npt; i += 256) {
        int b = i >> 12, n = i & (Npt - 1);
        float v = buf[((long)b * 512 + o) * Npt + n];
        s += v; s2 += (double)v * (double)v;
    }
    __shared__ double sh[256], sh2[256];
    __shared__ float smv, srv;
    sh[threadIdx.x] = s; sh2[threadIdx.x] = s2; __syncthreads();
    for (int st = 128; st > 0; st >>= 1) {
        if (threadIdx.x < st) { sh[threadIdx.x] += sh[threadIdx.x + st]; sh2[threadIdx.x] += sh2[threadIdx.x + st]; }
        __syncthreads();
    }
    if (threadIdx.x == 0) {
        double cnt = (double)(Bsz * Npt);
        double m = sh[0] / cnt;
        double var = sh2[0] / cnt - m * m;
        smv = (float)m;
        srv = rsqrtf((float)fmax(var, 0.0) + EPSBN);
    }
    __syncthreads();
    float m = smv, r = srv, g = gamma[o], be = beta[o];
    __shared__ float shm[256];
    for (int b = 0; b < Bsz; b++) {
        float best = -FLT_MAX;
        for (int n = threadIdx.x; n < Npt; n += 256) {
            float v = buf[((long)b * 512 + o) * Npt + n];
            best = fmaxf(best, lrelu((v - m) * r * g + be));
        }
        shm[threadIdx.x] = best; __syncthreads();
        for (int st = 128; st > 0; st >>= 1) {
            if (threadIdx.x < st) shm[threadIdx.x] = fmaxf(shm[threadIdx.x], shm[threadIdx.x + st]);
            __syncthreads();
        }
        if (threadIdx.x == 0) d_gmax[b * 512 + o] = shm[0];
        __syncthreads();
    }
}

// ---------------- fold W5[:,192:] @ broadcast(gmax) into a per-(b,o) bias ----------------
__global__ void k_bias5(const float* __restrict__ W5) {
    int t = blockIdx.x * 128 + threadIdx.x;
    int b = t >> 9, o = t & 511;
    float s = 0.f;
    #pragma unroll 8
    for (int c = 0; c < 512; c++)
        s += W5[(long)o * 704 + 192 + c] * d_gmax[b * 512 + c];
    d_bias5[b * 512 + o] = s;
}

// ---------------- final conv 128 -> 2 + bias ----------------
__global__ void k_final(const float* __restrict__ W8, const float* __restrict__ b8,
                        float* __restrict__ out) {
    int n = blockIdx.x * 256 + threadIdx.x, b = blockIdx.y;
    float s0 = b8[0], s1 = b8[1];
    #pragma unroll 8
    for (int c = 0; c < 128; c++) {
        float h = d_y7[((long)b * 128 + c) * Npt + n];
        s0 += W8[c] * h;
        s1 += W8[128 + c] * h;
    }
    out[(b * 2 + 0) * Npt + n] = s0;
    out[(b * 2 + 1) * Npt + n] = s1;
}

// ---------------- host ----------------
extern "C" void kernel_launch(void* const* d_in, const int* in_sizes, int n_in,
                              void* d_out, int out_size) {
    (void)in_sizes; (void)n_in; (void)out_size;
    const float* x   = (const float*)d_in[0];
    const float* W1  = (const float*)d_in[1];
    const float* W2  = (const float*)d_in[2];
    const float* W3  = (const float*)d_in[3];
    const float* W4  = (const float*)d_in[4];
    const float* W5  = (const float*)d_in[5];
    const float* W6  = (const float*)d_in[6];
    const float* W7  = (const float*)d_in[7];
    const float* W8  = (const float*)d_in[8];
    const float* b8  = (const float*)d_in[9];
    const float* g1 = (const float*)d_in[10], *bb1 = (const float*)d_in[11];
    const float* g2 = (const float*)d_in[12], *bb2 = (const float*)d_in[13];
    const float* g3 = (const float*)d_in[14], *bb3 = (const float*)d_in[15];
    const float* g4 = (const float*)d_in[16], *bb4 = (const float*)d_in[17];
    const float* g5 = (const float*)d_in[18], *bb5 = (const float*)d_in[19];
    const float* g6 = (const float*)d_in[20], *bb6 = (const float*)d_in[21];
    const float* g7 = (const float*)d_in[22], *bb7 = (const float*)d_in[23];

    static int smem_set = 0;
    if (!smem_set) {
        cudaFuncSetAttribute(k_dist_topk, cudaFuncAttributeMaxDynamicSharedMemorySize, DTK_SMEM);
        smem_set = 1;
    }

    void *pv;
    cudaGetSymbolAddress(&pv, d_xcat);  float* p_xcat = (float*)pv;
    cudaGetSymbolAddress(&pv, d_AC);    float* p_AC   = (float*)pv;
    cudaGetSymbolAddress(&pv, d_y4);    float* p_y4   = (float*)pv;
    cudaGetSymbolAddress(&pv, d_y5);    float* p_y5   = (float*)pv;
    cudaGetSymbolAddress(&pv, d_y6);    float* p_y6   = (float*)pv;
    cudaGetSymbolAddress(&pv, d_y7);    float* p_y7   = (float*)pv;
    cudaGetSymbolAddress(&pv, d_bias5); float* p_b5   = (float*)pv;
    cudaGetSymbolAddress(&pv, d_Wc2);   float* p_Wc2  = (float*)pv;
    cudaGetSymbolAddress(&pv, d_Wc3);   float* p_Wc3  = (float*)pv;

    // conv1 + BN + lrelu -> x1 (xcat[0:64))
    k_conv1<<<dim3(16, 64, 4), 256>>>(x, W1);
    k_statsapply<<<64, 256>>>(p_xcat, 192, 0, g1, bb1);

    // kNN round 1 on x1 (fused dist+topk)
    k_sqnorm<<<dim3(16, 4), 256>>>(0);
    k_dist_topk<<<dim3(4, 32, 4), 256, DTK_SMEM>>>(0);
    k_topk_merge<<<64, 256>>>();

    // edge-conv 2 -> x2 (xcat[64:128))
    k_prepw<<<64, 64>>>(W2, p_Wc2);
    k_gemm128<<<dim3(32, 1, 4), 256>>>(p_AC, p_xcat, p_Wc2, nullptr, 64, 64, 192, 0, 128, 0);
    k_edge_stats<<<64, 256>>>();
    k_edge_apply<<<dim3(16, 64, 4), 256>>>(g2, bb2, 64);

    // kNN round 2 on x2
    k_sqnorm<<<dim3(16, 4), 256>>>(64);
    k_dist_topk<<<dim3(4, 32, 4), 256, DTK_SMEM>>>(64);
    k_topk_merge<<<64, 256>>>();

    // edge-conv 3 -> x3 (xcat[128:192))
    k_prepw<<<64, 64>>>(W3, p_Wc3);
    k_gemm128<<<dim3(32, 1, 4), 256>>>(p_AC, p_xcat, p_Wc3, nullptr, 64, 64, 192, 64, 128, 0);
    k_edge_stats<<<64, 256>>>();
    k_edge_apply<<<dim3(16, 64, 4), 256>>>(g3, bb3, 128);

    // global branch: y4 = W4 @ x3; fused stats+BN+lrelu+max -> gmax; fold into bias5
    k_gemm128<<<dim3(32, 4, 4), 256>>>(p_y4, p_xcat, W4, nullptr, 64, 64, 192, 128, 512, 0);
    k_stats_gmax<<<512, 256>>>(p_y4, g4, bb4);
    k_bias5<<<16, 128>>>(W5);

    // W5 on [x1;x2;x3] (C=192) + bias5; BN; lrelu
    k_gemm128<<<dim3(32, 4, 4), 256>>>(p_y5, p_xcat, W5, p_b5, 192, 704, 192, 0, 512, 0);
    k_statsapply<<<512, 256>>>(p_y5, 512, 0, g5, bb5);

    // W6
    k_gemm128<<<dim3(32, 2, 4), 256>>>(p_y6, p_y5, W6, nullptr, 512, 512, 512, 0, 256, 0);
    k_statsapply<<<256, 256>>>(p_y6, 256, 0, g6, bb6);

    // W7
    k_gemm128<<<dim3(32, 1, 4), 256>>>(p_y7, p_y6, W7, nullptr, 256, 256, 256, 0, 128, 0);
    k_statsapply<<<128, 256>>>(p_y7, 128, 0, g7, bb7);

    // final 128 -> 2
    k_final<<<dim3(16, 4), 256>>>(W8, b8, (float*)d_out);
}

// round 5
// speedup vs baseline: 1.0386x; 1.0386x over previous
#include <cuda_runtime.h>
#include <math.h>
#include <float.h>

#define Bsz 4
#define Npt 4096
#define KNN 20
#define EPSBN 1e-5f
#define PARTS 4
#define PCOLS 1024
#define NROWS (Bsz * Npt)

// ---------------- scratch (device globals; no allocations) ----------------
__device__ float d_dist[(size_t)Bsz * Npt * Npt];   // 268 MB distance matrix
__device__ float d_xcat[Bsz * 192 * Npt];           // x1|x2|x3 concatenated
__device__ float d_AC[Bsz * 128 * Npt];             // A (0:64) | Cc (64:128)
__device__ float d_y5[Bsz * 512 * Npt];
__device__ float d_y4[Bsz * 512 * Npt];
__device__ float d_y6[Bsz * 256 * Npt];
__device__ float d_y7[Bsz * 128 * Npt];
__device__ float d_sq[Bsz * Npt];
__device__ int   d_idx[Bsz * Npt * KNN];
__device__ float d_gmax[Bsz * 512];
__device__ float d_bias5[Bsz * 512];
__device__ float d_Wc2[128 * 64], d_Wc3[128 * 64];
__device__ float d_ptv[PARTS * KNN * NROWS];
__device__ int   d_pti[PARTS * KNN * NROWS];
__device__ float d_mean[64];
__device__ float d_rstd[64];

__device__ __forceinline__ float lrelu(float v) { return v >= 0.f ? v : 0.2f * v; }

// register-resident sorted top-20 insert (descending; topv[19] = current min).
// Fully unrolled static indices -> stays in registers. Strict > keeps earlier index on ties.
__device__ __forceinline__ void top20_insert(float (&topv)[20], int (&topi)[20], float v, int idx) {
    if (v > topv[19]) {
        float cv = v; int ci = idx;
        #pragma unroll
        for (int t = 0; t < 20; t++) {
            if (cv > topv[t]) {
                float tv = topv[t]; int ti = topi[t];
                topv[t] = cv; topi[t] = ci;
                cv = tv; ci = ti;
            }
        }
    }
}

// ---------------- conv1: 3 -> 64 ----------------
__global__ void k_conv1(const float* __restrict__ x, const float* __restrict__ W1) {
    int n = blockIdx.x * 256 + threadIdx.x;
    int o = blockIdx.y, b = blockIdx.z;
    float v = W1[o * 3 + 0] * x[(b * 3 + 0) * Npt + n]
            + W1[o * 3 + 1] * x[(b * 3 + 1) * Npt + n]
            + W1[o * 3 + 2] * x[(b * 3 + 2) * Npt + n];
    d_xcat[((long)b * 192 + o) * Npt + n] = v;
}

// ---------------- fused BN stats + apply + lrelu (in place) ----------------
__global__ void k_statsapply(float* __restrict__ buf, int CT, int c0,
                             const float* __restrict__ gamma, const float* __restrict__ beta) {
    int o = blockIdx.x;
    double s = 0.0, s2 = 0.0;
    for (int i = threadIdx.x; i < Bsz * Npt; i += 256) {
        int b = i >> 12, n = i & (Npt - 1);
        float v = buf[((long)b * CT + c0 + o) * Npt + n];
        s += v; s2 += (double)v * (double)v;
    }
    __shared__ double sh[256], sh2[256];
    __shared__ float smv, srv;
    sh[threadIdx.x] = s; sh2[threadIdx.x] = s2; __syncthreads();
    for (int st = 128; st > 0; st >>= 1) {
        if (threadIdx.x < st) { sh[threadIdx.x] += sh[threadIdx.x + st]; sh2[threadIdx.x] += sh2[threadIdx.x + st]; }
        __syncthreads();
    }
    if (threadIdx.x == 0) {
        double cnt = (double)(Bsz * Npt);
        double m = sh[0] / cnt;
        double var = sh2[0] / cnt - m * m;
        smv = (float)m;
        srv = rsqrtf((float)fmax(var, 0.0) + EPSBN);
    }
    __syncthreads();
    float m = smv, r = srv, g = gamma[o], be = beta[o];
    for (int i = threadIdx.x; i < Bsz * Npt; i += 256) {
        int b = i >> 12, n = i & (Npt - 1);
        long off = ((long)b * CT + c0 + o) * Npt + n;
        buf[off] = lrelu((buf[off] - m) * r * g + be);
    }
}

// ---------------- squared norms ----------------
__global__ void k_sqnorm(int c0) {
    int n = blockIdx.x * 256 + threadIdx.x, b = blockIdx.y;
    float s = 0.f;
    #pragma unroll 8
    for (int c = 0; c < 64; c++) {
        float v = d_xcat[((long)b * 192 + c0 + c) * Npt + n];
        s += v * v;
    }
    d_sq[b * Npt + n] = s;
}

// ======== 128x128 tile, 8x8/thread distance GEMM ========
__global__ void __launch_bounds__(256, 1) k_dist128(int c0) {
    __shared__ float Qs[16][132];
    __shared__ float Ms[16][128];
    int b = blockIdx.z, q0 = blockIdx.y * 128, n0 = blockIdx.x * 128;
    int tid = threadIdx.x, tx = tid & 15, ty = tid >> 4;
    float acc[2][2][4][4] = {};
    const float* xb = d_xcat + ((long)b * 192 + c0) * Npt;
    #pragma unroll 1
    for (int ck = 0; ck < 64; ck += 16) {
        #pragma unroll
        for (int r = 0; r < 8; r++) {
            int idx = r * 256 + tid;
            int cc = idx >> 7, e = idx & 127;
            long rowoff = (long)(ck + cc) * Npt;
            Qs[cc][e] = xb[rowoff + q0 + e];
            Ms[cc][e] = xb[rowoff + n0 + e];
        }
        __syncthreads();
        #pragma unroll
        for (int k = 0; k < 16; k++) {
            float4 a0 = *(const float4*)&Qs[k][ty * 4];
            float4 a1 = *(const float4*)&Qs[k][64 + ty * 4];
            float4 b0 = *(const float4*)&Ms[k][tx * 4];
            float4 b1 = *(const float4*)&Ms[k][64 + tx * 4];
            float aa[2][4] = {{a0.x, a0.y, a0.z, a0.w}, {a1.x, a1.y, a1.z, a1.w}};
            float bb[2][4] = {{b0.x, b0.y, b0.z, b0.w}, {b1.x, b1.y, b1.z, b1.w}};
            #pragma unroll
            for (int ii = 0; ii < 2; ii++)
                #pragma unroll
                for (int i = 0; i < 4; i++)
                    #pragma unroll
                    for (int jj = 0; jj < 2; jj++)
                        #pragma unroll
                        for (int j = 0; j < 4; j++)
                            acc[ii][jj][i][j] += aa[ii][i] * bb[jj][j];
        }
        __syncthreads();
    }
    long bN = (long)b * Npt;
    float4 s0 = *(const float4*)&d_sq[bN + n0 + tx * 4];
    float4 s1 = *(const float4*)&d_sq[bN + n0 + 64 + tx * 4];
    float sn0[4] = {s0.x, s0.y, s0.z, s0.w};
    float sn1[4] = {s1.x, s1.y, s1.z, s1.w};
    #pragma unroll
    for (int ii = 0; ii < 2; ii++) {
        #pragma unroll
        for (int i = 0; i < 4; i++) {
            int q = q0 + ii * 64 + ty * 4 + i;
            float sqq = d_sq[bN + q];
            float* row = d_dist + (bN + q) * Npt + n0;
            float4 v0, v1;
            v0.x = 2.f * acc[ii][0][i][0] - sqq - sn0[0];
            v0.y = 2.f * acc[ii][0][i][1] - sqq - sn0[1];
            v0.z = 2.f * acc[ii][0][i][2] - sqq - sn0[2];
            v0.w = 2.f * acc[ii][0][i][3] - sqq - sn0[3];
            v1.x = 2.f * acc[ii][1][i][0] - sqq - sn1[0];
            v1.y = 2.f * acc[ii][1][i][1] - sqq - sn1[1];
            v1.z = 2.f * acc[ii][1][i][2] - sqq - sn1[2];
            v1.w = 2.f * acc[ii][1][i][3] - sqq - sn1[3];
            *(float4*)&row[tx * 4] = v0;
            *(float4*)&row[64 + tx * 4] = v1;
        }
    }
}

// ---------------- partial top-20: warp handles 32 rows over 1024 columns ----------------
__global__ void k_topk_part() {
    __shared__ float sh[4][32][33];
    int warp = threadIdx.x >> 5, lane = threadIdx.x & 31;
    int wg = blockIdx.x * 4 + warp;        // 0..2047
    int part = wg & 3;
    int rowBase = (wg >> 2) * 32;
    int c0base = part * PCOLS;
    float topv[20]; int topi[20];
    #pragma unroll
    for (int t = 0; t < 20; t++) { topv[t] = -FLT_MAX; topi[t] = c0base; }
    for (int c0 = c0base; c0 < c0base + PCOLS; c0 += 32) {
        #pragma unroll 8
        for (int rr = 0; rr < 32; rr++)
            sh[warp][rr][lane] = d_dist[((long)(rowBase + rr)) * Npt + c0 + lane];
        __syncwarp();
        #pragma unroll 4
        for (int j = 0; j < 32; j++) {
            float v = sh[warp][lane][j];
            top20_insert(topv, topi, v, c0 + j);
        }
        __syncwarp();
    }
    int row = rowBase + lane;
    #pragma unroll
    for (int t = 0; t < 20; t++) {
        d_ptv[(part * 20 + t) * NROWS + row] = topv[t];
        d_pti[(part * 20 + t) * NROWS + row] = topi[t];
    }
}

// ---------------- merge 4 partial top-20 lists (ascending part order keeps ties) ----------------
__global__ void k_topk_merge() {
    int row = blockIdx.x * 256 + threadIdx.x;
    float topv[20]; int topi[20];
    #pragma unroll
    for (int t = 0; t < 20; t++) { topv[t] = -FLT_MAX; topi[t] = 0; }
    for (int p = 0; p < PARTS; p++) {
        #pragma unroll
        for (int t = 0; t < 20; t++) {
            float v = d_ptv[(p * 20 + t) * NROWS + row];
            int ix = d_pti[(p * 20 + t) * NROWS + row];
            top20_insert(topv, topi, v, ix);
        }
    }
    #pragma unroll
    for (int t = 0; t < 20; t++) d_idx[row * KNN + t] = topi[t];
}

// ---------------- combined weight prep: rows 0:64 = W[:, :64], rows 64:128 = W[:,64:] - W[:, :64] ----------------
__global__ void k_prepw(const float* __restrict__ W, float* __restrict__ Wc) {
    int o = blockIdx.x, c = threadIdx.x;
    float a = W[o * 128 + c], bb = W[o * 128 + 64 + c];
    Wc[o * 64 + c] = a;
    Wc[(64 + o) * 64 + c] = bb - a;
}

// ======== 128x128 tile feature GEMM ========
__global__ void __launch_bounds__(256, 1) k_gemm128(
        float* __restrict__ out, const float* __restrict__ in,
        const float* __restrict__ W, const float* __restrict__ biasBO,
        int C, int ldw, int CTin, int c0in, int CTout, int c0out) {
    __shared__ float Ws[16][132];
    __shared__ float Xs[16][128];
    int b = blockIdx.z, o0 = blockIdx.y * 128, n0 = blockIdx.x * 128;
    int tid = threadIdx.x, tx = tid & 15, ty = tid >> 4;
    float acc[2][2][4][4] = {};
    const float* inB = in + ((long)b * CTin + c0in) * Npt + n0;
    #pragma unroll 1
    for (int ck = 0; ck < C; ck += 16) {
        #pragma unroll
        for (int r = 0; r < 8; r++) {
            int idx = r * 256 + tid;
            int oo = idx >> 4, cc = idx & 15;
            Ws[cc][oo] = W[(long)(o0 + oo) * ldw + ck + cc];
        }
        #pragma unroll
        for (int r = 0; r < 8; r++) {
            int idx = r * 256 + tid;
            int cc = idx >> 7, e = idx & 127;
            Xs[cc][e] = inB[(long)(ck + cc) * Npt + e];
        }
        __syncthreads();
        #pragma unroll
        for (int k = 0; k < 16; k++) {
            float4 a0 = *(const float4*)&Ws[k][ty * 4];
            float4 a1 = *(const float4*)&Ws[k][64 + ty * 4];
            float4 b0 = *(const float4*)&Xs[k][tx * 4];
            float4 b1 = *(const float4*)&Xs[k][64 + tx * 4];
            float aa[2][4] = {{a0.x, a0.y, a0.z, a0.w}, {a1.x, a1.y, a1.z, a1.w}};
            float bb[2][4] = {{b0.x, b0.y, b0.z, b0.w}, {b1.x, b1.y, b1.z, b1.w}};
            #pragma unroll
            for (int ii = 0; ii < 2; ii++)
                #pragma unroll
                for (int i = 0; i < 4; i++)
                    #pragma unroll
                    for (int jj = 0; jj < 2; jj++)
                        #pragma unroll
                        for (int j = 0; j < 4; j++)
                            acc[ii][jj][i][j] += aa[ii][i] * bb[jj][j];
        }
        __syncthreads();
    }
    #pragma unroll
    for (int ii = 0; ii < 2; ii++) {
        #pragma unroll
        for (int i = 0; i < 4; i++) {
            int o = o0 + ii * 64 + ty * 4 + i;
            float bias = biasBO ? biasBO[b * 512 + o] : 0.f;
            float* row = out + ((long)b * CTout + c0out + o) * Npt + n0;
            float4 v0, v1;
            v0.x = acc[ii][0][i][0] + bias; v0.y = acc[ii][0][i][1] + bias;
            v0.z = acc[ii][0][i][2] + bias; v0.w = acc[ii][0][i][3] + bias;
            v1.x = acc[ii][1][i][0] + bias; v1.y = acc[ii][1][i][1] + bias;
            v1.z = acc[ii][1][i][2] + bias; v1.w = acc[ii][1][i][3] + bias;
            *(float4*)&row[tx * 4] = v0;
            *(float4*)&row[64 + tx * 4] = v1;
        }
    }
}

// ---------------- edge-conv BN stats over (b, n, k) ----------------
__global__ void k_edge_stats() {
    int o = blockIdx.x;
    double s = 0.0, s2 = 0.0;
    const int TOT = Bsz * Npt * KNN;
    for (int i = threadIdx.x; i < TOT; i += 256) {
        int b = i / (Npt * KNN);
        int rem = i - b * (Npt * KNN);
        int n = rem / KNN;
        int j = d_idx[i];
        float v = d_AC[((long)b * 128 + o) * Npt + j] + d_AC[((long)b * 128 + 64 + o) * Npt + n];
        s += v; s2 += (double)v * (double)v;
    }
    __shared__ double sh[256], sh2[256];
    sh[threadIdx.x] = s; sh2[threadIdx.x] = s2; __syncthreads();
    for (int st = 128; st > 0; st >>= 1) {
        if (threadIdx.x < st) { sh[threadIdx.x] += sh[threadIdx.x + st]; sh2[threadIdx.x] += sh2[threadIdx.x + st]; }
        __syncthreads();
    }
    if (threadIdx.x == 0) {
        double cnt = (double)TOT;
        double m = sh[0] / cnt;
        double var = sh2[0] / cnt - m * m;
        d_mean[o] = (float)m;
        d_rstd[o] = rsqrtf((float)fmax(var, 0.0) + EPSBN);
    }
}

// ---------------- edge-conv BN+lrelu+max_k ----------------
__global__ void k_edge_apply(const float* __restrict__ gamma, const float* __restrict__ beta, int c0out) {
    int n = blockIdx.x * 256 + threadIdx.x, o = blockIdx.y, b = blockIdx.z;
    float m = d_mean[o], r = d_rstd[o], g = gamma[o], be = beta[o];
    const float* Ab = d_AC + ((long)b * 128 + o) * Npt;
    float cc = d_AC[((long)b * 128 + 64 + o) * Npt + n];
    const int* ip = d_idx + (b * Npt + n) * KNN;
    float best = -FLT_MAX;
    #pragma unroll 4
    for (int k = 0; k < KNN; k++) {
        float v = Ab[ip[k]] + cc;
        v = lrelu((v - m) * r * g + be);
        best = fmaxf(best, v);
    }
    d_xcat[((long)b * 192 + c0out + o) * Npt + n] = best;
}

// ---------------- fused stats + BN + lrelu + max over n -> gmax ----------------
__global__ void k_stats_gmax(const float* __restrict__ buf,
                             const float* __restrict__ gamma, const float* __restrict__ beta) {
    int o = blockIdx.x;  // 512
    double s = 0.0, s2 = 0.0;
    for (int i = threadIdx.x; i < Bsz * Npt; i += 256) {
        int b = i >> 12, n = i & (Npt - 1);
        float v = buf[((long)b * 512 + o) * Npt + n];
        s += v; s2 += (double)v * (double)v;
    }
    __shared__ double sh[256], sh2[256];
    __shared__ float smv, srv;
    sh[threadIdx.x] = s; sh2[threadIdx.x] = s2; __syncthreads();
    for (int st = 128; st > 0; st >>= 1) {
        if (threadIdx.x < st) { sh[threadIdx.x] += sh[threadIdx.x + st]; sh2[threadIdx.x] += sh2[threadIdx.x + st]; }
        __syncthreads();
    }
    if (threadIdx.x == 0) {
        double cnt = (double)(Bsz * Npt);
        double m = sh[0] / cnt;
        double var = sh2[0] / cnt - m * m;
        smv = (float)m;
        srv = rsqrtf((float)fmax(var, 0.0) + EPSBN);
    }
    __syncthreads();
    float m = smv, r = srv, g = gamma[o], be = beta[o];
    __shared__ float shm[256];
    for (int b = 0; b < Bsz; b++) {
        float best = -FLT_MAX;
        for (int n = threadIdx.x; n < Npt; n += 256) {
            float v = buf[((long)b * 512 + o) * Npt + n];
            best = fmaxf(best, lrelu((v - m) * r * g + be));
        }
        shm[threadIdx.x] = best; __syncthreads();
        for (int st = 128; st > 0; st >>= 1) {
            if (threadIdx.x < st) shm[threadIdx.x] = fmaxf(shm[threadIdx.x], shm[threadIdx.x + st]);
            __syncthreads();
        }
        if (threadIdx.x == 0) d_gmax[b * 512 + o] = shm[0];
        __syncthreads();
    }
}

// ---------------- fold W5[:,192:] @ broadcast(gmax) into a per-(b,o) bias ----------------
__global__ void k_bias5(const float* __restrict__ W5) {
    int t = blockIdx.x * 128 + threadIdx.x;
    int b = t >> 9, o = t & 511;
    float s = 0.f;
    #pragma unroll 8
    for (int c = 0; c < 512; c++)
        s += W5[(long)o * 704 + 192 + c] * d_gmax[b * 512 + c];
    d_bias5[b * 512 + o] = s;
}

// ---------------- final conv 128 -> 2 + bias ----------------
__global__ void k_final(const float* __restrict__ W8, const float* __restrict__ b8,
                        float* __restrict__ out) {
    int n = blockIdx.x * 256 + threadIdx.x, b = blockIdx.y;
    float s0 = b8[0], s1 = b8[1];
    #pragma unroll 8
    for (int c = 0; c < 128; c++) {
        float h = d_y7[((long)b * 128 + c) * Npt + n];
        s0 += W8[c] * h;
        s1 += W8[128 + c] * h;
    }
    out[(b * 2 + 0) * Npt + n] = s0;
    out[(b * 2 + 1) * Npt + n] = s1;
}

// ---------------- host ----------------
extern "C" void kernel_launch(void* const* d_in, const int* in_sizes, int n_in,
                              void* d_out, int out_size) {
    (void)in_sizes; (void)n_in; (void)out_size;
    const float* x   = (const float*)d_in[0];
    const float* W1  = (const float*)d_in[1];
    const float* W2  = (const float*)d_in[2];
    const float* W3  = (const float*)d_in[3];
    const float* W4  = (const float*)d_in[4];
    const float* W5  = (const float*)d_in[5];
    const float* W6  = (const float*)d_in[6];
    const float* W7  = (const float*)d_in[7];
    const float* W8  = (const float*)d_in[8];
    const float* b8  = (const float*)d_in[9];
    const float* g1 = (const float*)d_in[10], *bb1 = (const float*)d_in[11];
    const float* g2 = (const float*)d_in[12], *bb2 = (const float*)d_in[13];
    const float* g3 = (const float*)d_in[14], *bb3 = (const float*)d_in[15];
    const float* g4 = (const float*)d_in[16], *bb4 = (const float*)d_in[17];
    const float* g5 = (const float*)d_in[18], *bb5 = (const float*)d_in[19];
    const float* g6 = (const float*)d_in[20], *bb6 = (const float*)d_in[21];
    const float* g7 = (const float*)d_in[22], *bb7 = (const float*)d_in[23];

    void *pv;
    cudaGetSymbolAddress(&pv, d_xcat);  float* p_xcat = (float*)pv;
    cudaGetSymbolAddress(&pv, d_AC);    float* p_AC   = (float*)pv;
    cudaGetSymbolAddress(&pv, d_y4);    float* p_y4   = (float*)pv;
    cudaGetSymbolAddress(&pv, d_y5);    float* p_y5   = (float*)pv;
    cudaGetSymbolAddress(&pv, d_y6);    float* p_y6   = (float*)pv;
    cudaGetSymbolAddress(&pv, d_y7);    float* p_y7   = (float*)pv;
    cudaGetSymbolAddress(&pv, d_bias5); float* p_b5   = (float*)pv;
    cudaGetSymbolAddress(&pv, d_Wc2);   float* p_Wc2  = (float*)pv;
    cudaGetSymbolAddress(&pv, d_Wc3);   float* p_Wc3  = (float*)pv;

    // conv1 + BN + lrelu -> x1 (xcat[0:64))
    k_conv1<<<dim3(16, 64, 4), 256>>>(x, W1);
    k_statsapply<<<64, 256>>>(p_xcat, 192, 0, g1, bb1);

    // kNN round 1 on x1
    k_sqnorm<<<dim3(16, 4), 256>>>(0);
    k_dist128<<<dim3(32, 32, 4), 256>>>(0);
    k_topk_part<<<512, 128>>>();
    k_topk_merge<<<64, 256>>>();

    // edge-conv 2 -> x2 (xcat[64:128))
    k_prepw<<<64, 64>>>(W2, p_Wc2);
    k_gemm128<<<dim3(32, 1, 4), 256>>>(p_AC, p_xcat, p_Wc2, nullptr, 64, 64, 192, 0, 128, 0);
    k_edge_stats<<<64, 256>>>();
    k_edge_apply<<<dim3(16, 64, 4), 256>>>(g2, bb2, 64);

    // kNN round 2 on x2
    k_sqnorm<<<dim3(16, 4), 256>>>(64);
    k_dist128<<<dim3(32, 32, 4), 256>>>(64);
    k_topk_part<<<512, 128>>>();
    k_topk_merge<<<64, 256>>>();

    // edge-conv 3 -> x3 (xcat[128:192))
    k_prepw<<<64, 64>>>(W3, p_Wc3);
    k_gemm128<<<dim3(32, 1, 4), 256>>>(p_AC, p_xcat, p_Wc3, nullptr, 64, 64, 192, 64, 128, 0);
    k_edge_stats<<<64, 256>>>();
    k_edge_apply<<<dim3(16, 64, 4), 256>>>(g3, bb3, 128);

    // global branch: y4 = W4 @ x3; fused stats+BN+lrelu+max -> gmax; fold into bias5
    k_gemm128<<<dim3(32, 4, 4), 256>>>(p_y4, p_xcat, W4, nullptr, 64, 64, 192, 128, 512, 0);
    k_stats_gmax<<<512, 256>>>(p_y4, g4, bb4);
    k_bias5<<<16, 128>>>(W5);

    // W5 on [x1;x2;x3] (C=192) + bias5; BN; lrelu
    k_gemm128<<<dim3(32, 4, 4), 256>>>(p_y5, p_xcat, W5, p_b5, 192, 704, 192, 0, 512, 0);
    k_statsapply<<<512, 256>>>(p_y5, 512, 0, g5, bb5);

    // W6
    k_gemm128<<<dim3(32, 2, 4), 256>>>(p_y6, p_y5, W6, nullptr, 512, 512, 512, 0, 256, 0);
    k_statsapply<<<256, 256>>>(p_y6, 256, 0, g6, bb6);

    // W7
    k_gemm128<<<dim3(32, 1, 4), 256>>>(p_y7, p_y6, W7, nullptr, 256, 256, 256, 0, 128, 0);
    k_statsapply<<<128, 256>>>(p_y7, 128, 0, g7, bb7);

    // final 128 -> 2
    k_final<<<dim3(16, 4), 256>>>(W8, b8, (float*)d_out);
}

// round 6
// speedup vs baseline: 1.4053x; 1.3531x over previous
#include <cuda_runtime.h>
#include <math.h>
#include <float.h>

#define Bsz 4
#define Npt 4096
#define KNN 20
#define EPSBN 1e-5f
#define PARTS 4
#define PCOLS 1024
#define NROWS (Bsz * Npt)

// ---------------- scratch (device globals; no allocations) ----------------
__device__ float d_dist[(size_t)Bsz * Npt * Npt];   // 268 MB distance matrix
__device__ float d_xcat[Bsz * 192 * Npt];           // x1|x2|x3 concatenated
__device__ float d_AC[Bsz * 128 * Npt];             // A (0:64) | Cc (64:128)
__device__ float d_y5[Bsz * 512 * Npt];
__device__ float d_y4[Bsz * 512 * Npt];
__device__ float d_y6[Bsz * 256 * Npt];
__device__ float d_y7[Bsz * 128 * Npt];
__device__ int   d_idx[Bsz * Npt * KNN];
__device__ float d_gmax[Bsz * 512];
__device__ float d_bias5[Bsz * 512];
__device__ float d_Wc2[128 * 64], d_Wc3[128 * 64];
__device__ float d_ptv[PARTS * KNN * NROWS];
__device__ int   d_pti[PARTS * KNN * NROWS];
__device__ float d_mean[64];
__device__ float d_rstd[64];
__device__ float d_espart[64 * 8 * 2];   // edge-stats partials (s, s2)

__device__ __forceinline__ float lrelu(float v) { return v >= 0.f ? v : 0.2f * v; }

// Kahan-compensated fp32 accumulator
__device__ __forceinline__ void kadd(float& s, float& c, float v) {
    float y = v - c;
    float t = s + y;
    c = (t - s) - y;
    s = t;
}

// register-resident sorted top-20 insert (descending; topv[19] = current min).
__device__ __forceinline__ void top20_insert(float (&topv)[20], int (&topi)[20], float v, int idx) {
    if (v > topv[19]) {
        float cv = v; int ci = idx;
        #pragma unroll
        for (int t = 0; t < 20; t++) {
            if (cv > topv[t]) {
                float tv = topv[t]; int ti = topi[t];
                topv[t] = cv; topi[t] = ci;
                cv = tv; ci = ti;
            }
        }
    }
}

// ---------------- conv1: 3 -> 64 ----------------
__global__ void k_conv1(const float* __restrict__ x, const float* __restrict__ W1) {
    int n = blockIdx.x * 256 + threadIdx.x;
    int o = blockIdx.y, b = blockIdx.z;
    float v = W1[o * 3 + 0] * x[(b * 3 + 0) * Npt + n]
            + W1[o * 3 + 1] * x[(b * 3 + 1) * Npt + n]
            + W1[o * 3 + 2] * x[(b * 3 + 2) * Npt + n];
    d_xcat[((long)b * 192 + o) * Npt + n] = v;
}

// ---------------- fused BN stats + apply + lrelu (in place, fp32 Kahan) ----------------
__global__ void k_statsapply(float* __restrict__ buf, int CT, int c0,
                             const float* __restrict__ gamma, const float* __restrict__ beta) {
    int o = blockIdx.x;
    float s = 0.f, sc = 0.f, s2 = 0.f, s2c = 0.f;
    for (int i = threadIdx.x; i < Bsz * Npt; i += 256) {
        int b = i >> 12, n = i & (Npt - 1);
        float v = buf[((long)b * CT + c0 + o) * Npt + n];
        kadd(s, sc, v);
        kadd(s2, s2c, v * v);
    }
    __shared__ float sh[256], sh2[256];
    __shared__ float smv, srv;
    sh[threadIdx.x] = s; sh2[threadIdx.x] = s2; __syncthreads();
    for (int st = 128; st > 0; st >>= 1) {
        if (threadIdx.x < st) { sh[threadIdx.x] += sh[threadIdx.x + st]; sh2[threadIdx.x] += sh2[threadIdx.x + st]; }
        __syncthreads();
    }
    if (threadIdx.x == 0) {
        float cnt = (float)(Bsz * Npt);
        float m = sh[0] / cnt;
        float var = sh2[0] / cnt - m * m;
        smv = m;
        srv = rsqrtf(fmaxf(var, 0.f) + EPSBN);
    }
    __syncthreads();
    float m = smv, r = srv, g = gamma[o], be = beta[o];
    for (int i = threadIdx.x; i < Bsz * Npt; i += 256) {
        int b = i >> 12, n = i & (Npt - 1);
        long off = ((long)b * CT + c0 + o) * Npt + n;
        buf[off] = lrelu((buf[off] - m) * r * g + be);
    }
}

// ======== 128x128 tile, 8x8/thread distance GEMM (column norms computed in-kernel) ========
// writes 2*dot - sq[n]  (row-constant sq[q] dropped: per-row order preserved)
__global__ void __launch_bounds__(256, 1) k_dist128(int c0) {
    __shared__ float Qs[16][132];
    __shared__ float Ms[16][128];
    __shared__ float sqM[128];
    int b = blockIdx.z, q0 = blockIdx.y * 128, n0 = blockIdx.x * 128;
    int tid = threadIdx.x, tx = tid & 15, ty = tid >> 4;
    float acc[2][2][4][4] = {};
    float myssq = 0.f;
    const float* xb = d_xcat + ((long)b * 192 + c0) * Npt;
    #pragma unroll 1
    for (int ck = 0; ck < 64; ck += 16) {
        #pragma unroll
        for (int r = 0; r < 8; r++) {
            int idx = r * 256 + tid;
            int cc = idx >> 7, e = idx & 127;
            long rowoff = (long)(ck + cc) * Npt;
            Qs[cc][e] = xb[rowoff + q0 + e];
            Ms[cc][e] = xb[rowoff + n0 + e];
        }
        __syncthreads();
        if (tid < 128) {
            #pragma unroll
            for (int cc = 0; cc < 16; cc++) {
                float v = Ms[cc][tid];
                myssq += v * v;
            }
        }
        #pragma unroll
        for (int k = 0; k < 16; k++) {
            float4 a0 = *(const float4*)&Qs[k][ty * 4];
            float4 a1 = *(const float4*)&Qs[k][64 + ty * 4];
            float4 b0 = *(const float4*)&Ms[k][tx * 4];
            float4 b1 = *(const float4*)&Ms[k][64 + tx * 4];
            float aa[2][4] = {{a0.x, a0.y, a0.z, a0.w}, {a1.x, a1.y, a1.z, a1.w}};
            float bb[2][4] = {{b0.x, b0.y, b0.z, b0.w}, {b1.x, b1.y, b1.z, b1.w}};
            #pragma unroll
            for (int ii = 0; ii < 2; ii++)
                #pragma unroll
                for (int i = 0; i < 4; i++)
                    #pragma unroll
                    for (int jj = 0; jj < 2; jj++)
                        #pragma unroll
                        for (int j = 0; j < 4; j++)
                            acc[ii][jj][i][j] += aa[ii][i] * bb[jj][j];
        }
        __syncthreads();
    }
    if (tid < 128) sqM[tid] = myssq;
    __syncthreads();
    long bN = (long)b * Npt;
    float sn0[4], sn1[4];
    #pragma unroll
    for (int j = 0; j < 4; j++) {
        sn0[j] = sqM[tx * 4 + j];
        sn1[j] = sqM[64 + tx * 4 + j];
    }
    #pragma unroll
    for (int ii = 0; ii < 2; ii++) {
        #pragma unroll
        for (int i = 0; i < 4; i++) {
            int q = q0 + ii * 64 + ty * 4 + i;
            float* row = d_dist + (bN + q) * Npt + n0;
            float4 v0, v1;
            v0.x = 2.f * acc[ii][0][i][0] - sn0[0];
            v0.y = 2.f * acc[ii][0][i][1] - sn0[1];
            v0.z = 2.f * acc[ii][0][i][2] - sn0[2];
            v0.w = 2.f * acc[ii][0][i][3] - sn0[3];
            v1.x = 2.f * acc[ii][1][i][0] - sn1[0];
            v1.y = 2.f * acc[ii][1][i][1] - sn1[1];
            v1.z = 2.f * acc[ii][1][i][2] - sn1[2];
            v1.w = 2.f * acc[ii][1][i][3] - sn1[3];
            *(float4*)&row[tx * 4] = v0;
            *(float4*)&row[64 + tx * 4] = v1;
        }
    }
}

// ---------------- partial top-20: warp handles 32 rows over 1024 columns ----------------
__global__ void k_topk_part() {
    __shared__ float sh[4][32][33];
    int warp = threadIdx.x >> 5, lane = threadIdx.x & 31;
    int wg = blockIdx.x * 4 + warp;        // 0..2047
    int part = wg & 3;
    int rowBase = (wg >> 2) * 32;
    int c0base = part * PCOLS;
    float topv[20]; int topi[20];
    #pragma unroll
    for (int t = 0; t < 20; t++) { topv[t] = -FLT_MAX; topi[t] = c0base; }
    for (int c0 = c0base; c0 < c0base + PCOLS; c0 += 32) {
        #pragma unroll 8
        for (int rr = 0; rr < 32; rr++)
            sh[warp][rr][lane] = d_dist[((long)(rowBase + rr)) * Npt + c0 + lane];
        __syncwarp();
        #pragma unroll 4
        for (int j = 0; j < 32; j++) {
            float v = sh[warp][lane][j];
            top20_insert(topv, topi, v, c0 + j);
        }
        __syncwarp();
    }
    int row = rowBase + lane;
    #pragma unroll
    for (int t = 0; t < 20; t++) {
        d_ptv[(part * 20 + t) * NROWS + row] = topv[t];
        d_pti[(part * 20 + t) * NROWS + row] = topi[t];
    }
}

// ---------------- merge 4 partial top-20 lists (ascending part order keeps ties) ----------------
__global__ void k_topk_merge() {
    int row = blockIdx.x * 256 + threadIdx.x;
    float topv[20]; int topi[20];
    #pragma unroll
    for (int t = 0; t < 20; t++) { topv[t] = -FLT_MAX; topi[t] = 0; }
    for (int p = 0; p < PARTS; p++) {
        #pragma unroll
        for (int t = 0; t < 20; t++) {
            float v = d_ptv[(p * 20 + t) * NROWS + row];
            int ix = d_pti[(p * 20 + t) * NROWS + row];
            top20_insert(topv, topi, v, ix);
        }
    }
    #pragma unroll
    for (int t = 0; t < 20; t++) d_idx[row * KNN + t] = topi[t];
}

// ---------------- combined weight prep ----------------
__global__ void k_prepw(const float* __restrict__ W, float* __restrict__ Wc) {
    int o = blockIdx.x, c = threadIdx.x;
    float a = W[o * 128 + c], bb = W[o * 128 + 64 + c];
    Wc[o * 64 + c] = a;
    Wc[(64 + o) * 64 + c] = bb - a;
}

// ======== 128x128 tile feature GEMM ========
__global__ void __launch_bounds__(256, 1) k_gemm128(
        float* __restrict__ out, const float* __restrict__ in,
        const float* __restrict__ W, const float* __restrict__ biasBO,
        int C, int ldw, int CTin, int c0in, int CTout, int c0out) {
    __shared__ float Ws[16][132];
    __shared__ float Xs[16][128];
    int b = blockIdx.z, o0 = blockIdx.y * 128, n0 = blockIdx.x * 128;
    int tid = threadIdx.x, tx = tid & 15, ty = tid >> 4;
    float acc[2][2][4][4] = {};
    const float* inB = in + ((long)b * CTin + c0in) * Npt + n0;
    #pragma unroll 1
    for (int ck = 0; ck < C; ck += 16) {
        #pragma unroll
        for (int r = 0; r < 8; r++) {
            int idx = r * 256 + tid;
            int oo = idx >> 4, cc = idx & 15;
            Ws[cc][oo] = W[(long)(o0 + oo) * ldw + ck + cc];
        }
        #pragma unroll
        for (int r = 0; r < 8; r++) {
            int idx = r * 256 + tid;
            int cc = idx >> 7, e = idx & 127;
            Xs[cc][e] = inB[(long)(ck + cc) * Npt + e];
        }
        __syncthreads();
        #pragma unroll
        for (int k = 0; k < 16; k++) {
            float4 a0 = *(const float4*)&Ws[k][ty * 4];
            float4 a1 = *(const float4*)&Ws[k][64 + ty * 4];
            float4 b0 = *(const float4*)&Xs[k][tx * 4];
            float4 b1 = *(const float4*)&Xs[k][64 + tx * 4];
            float aa[2][4] = {{a0.x, a0.y, a0.z, a0.w}, {a1.x, a1.y, a1.z, a1.w}};
            float bb[2][4] = {{b0.x, b0.y, b0.z, b0.w}, {b1.x, b1.y, b1.z, b1.w}};
            #pragma unroll
            for (int ii = 0; ii < 2; ii++)
                #pragma unroll
                for (int i = 0; i < 4; i++)
                    #pragma unroll
                    for (int jj = 0; jj < 2; jj++)
                        #pragma unroll
                        for (int j = 0; j < 4; j++)
                            acc[ii][jj][i][j] += aa[ii][i] * bb[jj][j];
        }
        __syncthreads();
    }
    #pragma unroll
    for (int ii = 0; ii < 2; ii++) {
        #pragma unroll
        for (int i = 0; i < 4; i++) {
            int o = o0 + ii * 64 + ty * 4 + i;
            float bias = biasBO ? biasBO[b * 512 + o] : 0.f;
            float* row = out + ((long)b * CTout + c0out + o) * Npt + n0;
            float4 v0, v1;
            v0.x = acc[ii][0][i][0] + bias; v0.y = acc[ii][0][i][1] + bias;
            v0.z = acc[ii][0][i][2] + bias; v0.w = acc[ii][0][i][3] + bias;
            v1.x = acc[ii][1][i][0] + bias; v1.y = acc[ii][1][i][1] + bias;
            v1.z = acc[ii][1][i][2] + bias; v1.w = acc[ii][1][i][3] + bias;
            *(float4*)&row[tx * 4] = v0;
            *(float4*)&row[64 + tx * 4] = v1;
        }
    }
}

// ---------------- edge-conv BN stats: stage 1 (64 channels x 8 slices) ----------------
__global__ void k_edge_stats_part() {
    int o = blockIdx.x, slice = blockIdx.y;
    int tid = threadIdx.x;
    float s = 0.f, sc = 0.f, s2 = 0.f, s2c = 0.f;
    #pragma unroll 1
    for (int b = 0; b < Bsz; b++) {
        const float* Ab = d_AC + ((long)b * 128 + o) * Npt;
        const float* Cb = d_AC + ((long)b * 128 + 64 + o) * Npt;
        #pragma unroll 1
        for (int n = slice * 512 + tid; n < (slice + 1) * 512; n += 256) {
            float cc = Cb[n];
            const int* ip = d_idx + ((long)(b * Npt + n)) * KNN;
            #pragma unroll 4
            for (int k = 0; k < KNN; k++) {
                float v = Ab[ip[k]] + cc;
                kadd(s, sc, v);
                kadd(s2, s2c, v * v);
            }
        }
    }
    __shared__ float sh[256], sh2[256];
    sh[tid] = s; sh2[tid] = s2; __syncthreads();
    for (int st = 128; st > 0; st >>= 1) {
        if (tid < st) { sh[tid] += sh[tid + st]; sh2[tid] += sh2[tid + st]; }
        __syncthreads();
    }
    if (tid == 0) {
        d_espart[(o * 8 + slice) * 2 + 0] = sh[0];
        d_espart[(o * 8 + slice) * 2 + 1] = sh2[0];
    }
}

// ---------------- edge-conv BN stats: finalize ----------------
__global__ void k_edge_stats_fin() {
    int o = threadIdx.x;  // 64
    float s = 0.f, s2 = 0.f;
    #pragma unroll
    for (int p = 0; p < 8; p++) {
        s += d_espart[(o * 8 + p) * 2 + 0];
        s2 += d_espart[(o * 8 + p) * 2 + 1];
    }
    float cnt = (float)(Bsz * Npt * KNN);
    float m = s / cnt;
    float var = s2 / cnt - m * m;
    d_mean[o] = m;
    d_rstd[o] = rsqrtf(fmaxf(var, 0.f) + EPSBN);
}

// ---------------- edge-conv BN+lrelu+max_k ----------------
__global__ void k_edge_apply(const float* __restrict__ gamma, const float* __restrict__ beta, int c0out) {
    int n = blockIdx.x * 256 + threadIdx.x, o = blockIdx.y, b = blockIdx.z;
    float m = d_mean[o], r = d_rstd[o], g = gamma[o], be = beta[o];
    const float* Ab = d_AC + ((long)b * 128 + o) * Npt;
    float cc = d_AC[((long)b * 128 + 64 + o) * Npt + n];
    const int* ip = d_idx + (b * Npt + n) * KNN;
    float best = -FLT_MAX;
    #pragma unroll 4
    for (int k = 0; k < KNN; k++) {
        float v = Ab[ip[k]] + cc;
        v = lrelu((v - m) * r * g + be);
        best = fmaxf(best, v);
    }
    d_xcat[((long)b * 192 + c0out + o) * Npt + n] = best;
}

// ---------------- fused stats + BN + lrelu + max over n -> gmax (fp32 Kahan) ----------------
__global__ void k_stats_gmax(const float* __restrict__ buf,
                             const float* __restrict__ gamma, const float* __restrict__ beta) {
    int o = blockIdx.x;  // 512
    float s = 0.f, sc = 0.f, s2 = 0.f, s2c = 0.f;
    for (int i = threadIdx.x; i < Bsz * Npt; i += 256) {
        int b = i >> 12, n = i & (Npt - 1);
        float v = buf[((long)b * 512 + o) * Npt + n];
        kadd(s, sc, v);
        kadd(s2, s2c, v * v);
    }
    __shared__ float sh[256], sh2[256];
    __shared__ float smv, srv;
    sh[threadIdx.x] = s; sh2[threadIdx.x] = s2; __syncthreads();
    for (int st = 128; st > 0; st >>= 1) {
        if (threadIdx.x < st) { sh[threadIdx.x] += sh[threadIdx.x + st]; sh2[threadIdx.x] += sh2[threadIdx.x + st]; }
        __syncthreads();
    }
    if (threadIdx.x == 0) {
        float cnt = (float)(Bsz * Npt);
        float m = sh[0] / cnt;
        float var = sh2[0] / cnt - m * m;
        smv = m;
        srv = rsqrtf(fmaxf(var, 0.f) + EPSBN);
    }
    __syncthreads();
    float m = smv, r = srv, g = gamma[o], be = beta[o];
    __shared__ float shm[256];
    for (int b = 0; b < Bsz; b++) {
        float best = -FLT_MAX;
        for (int n = threadIdx.x; n < Npt; n += 256) {
            float v = buf[((long)b * 512 + o) * Npt + n];
            best = fmaxf(best, lrelu((v - m) * r * g + be));
        }
        shm[threadIdx.x] = best; __syncthreads();
        for (int st = 128; st > 0; st >>= 1) {
            if (threadIdx.x < st) shm[threadIdx.x] = fmaxf(shm[threadIdx.x], shm[threadIdx.x + st]);
            __syncthreads();
        }
        if (threadIdx.x == 0) d_gmax[b * 512 + o] = shm[0];
        __syncthreads();
    }
}

// ---------------- fold W5[:,192:] @ broadcast(gmax) into a per-(b,o) bias ----------------
__global__ void k_bias5(const float* __restrict__ W5) {
    int t = blockIdx.x * 128 + threadIdx.x;
    int b = t >> 9, o = t & 511;
    float s = 0.f;
    #pragma unroll 8
    for (int c = 0; c < 512; c++)
        s += W5[(long)o * 704 + 192 + c] * d_gmax[b * 512 + c];
    d_bias5[b * 512 + o] = s;
}

// ---------------- final conv 128 -> 2 + bias ----------------
__global__ void k_final(const float* __restrict__ W8, const float* __restrict__ b8,
                        float* __restrict__ out) {
    int n = blockIdx.x * 256 + threadIdx.x, b = blockIdx.y;
    float s0 = b8[0], s1 = b8[1];
    #pragma unroll 8
    for (int c = 0; c < 128; c++) {
        float h = d_y7[((long)b * 128 + c) * Npt + n];
        s0 += W8[c] * h;
        s1 += W8[128 + c] * h;
    }
    out[(b * 2 + 0) * Npt + n] = s0;
    out[(b * 2 + 1) * Npt + n] = s1;
}

// ---------------- host ----------------
extern "C" void kernel_launch(void* const* d_in, const int* in_sizes, int n_in,
                              void* d_out, int out_size) {
    (void)in_sizes; (void)n_in; (void)out_size;
    const float* x   = (const float*)d_in[0];
    const float* W1  = (const float*)d_in[1];
    const float* W2  = (const float*)d_in[2];
    const float* W3  = (const float*)d_in[3];
    const float* W4  = (const float*)d_in[4];
    const float* W5  = (const float*)d_in[5];
    const float* W6  = (const float*)d_in[6];
    const float* W7  = (const float*)d_in[7];
    const float* W8  = (const float*)d_in[8];
    const float* b8  = (const float*)d_in[9];
    const float* g1 = (const float*)d_in[10], *bb1 = (const float*)d_in[11];
    const float* g2 = (const float*)d_in[12], *bb2 = (const float*)d_in[13];
    const float* g3 = (const float*)d_in[14], *bb3 = (const float*)d_in[15];
    const float* g4 = (const float*)d_in[16], *bb4 = (const float*)d_in[17];
    const float* g5 = (const float*)d_in[18], *bb5 = (const float*)d_in[19];
    const float* g6 = (const float*)d_in[20], *bb6 = (const float*)d_in[21];
    const float* g7 = (const float*)d_in[22], *bb7 = (const float*)d_in[23];

    void *pv;
    cudaGetSymbolAddress(&pv, d_xcat);  float* p_xcat = (float*)pv;
    cudaGetSymbolAddress(&pv, d_AC);    float* p_AC   = (float*)pv;
    cudaGetSymbolAddress(&pv, d_y4);    float* p_y4   = (float*)pv;
    cudaGetSymbolAddress(&pv, d_y5);    float* p_y5   = (float*)pv;
    cudaGetSymbolAddress(&pv, d_y6);    float* p_y6   = (float*)pv;
    cudaGetSymbolAddress(&pv, d_y7);    float* p_y7   = (float*)pv;
    cudaGetSymbolAddress(&pv, d_bias5); float* p_b5   = (float*)pv;
    cudaGetSymbolAddress(&pv, d_Wc2);   float* p_Wc2  = (float*)pv;
    cudaGetSymbolAddress(&pv, d_Wc3);   float* p_Wc3  = (float*)pv;

    // conv1 + BN + lrelu -> x1 (xcat[0:64))
    k_conv1<<<dim3(16, 64, 4), 256>>>(x, W1);            // launch 0
    k_statsapply<<<64, 256>>>(p_xcat, 192, 0, g1, bb1);  // launch 1

    // kNN round 1 on x1 (sqnorm folded into dist)
    k_dist128<<<dim3(32, 32, 4), 256>>>(0);              // launch 2
    k_topk_part<<<512, 128>>>();                         // launch 3 (profiled slot)
    k_topk_merge<<<64, 256>>>();

    // edge-conv 2 -> x2 (xcat[64:128))
    k_prepw<<<64, 64>>>(W2, p_Wc2);
    k_gemm128<<<dim3(32, 1, 4), 256>>>(p_AC, p_xcat, p_Wc2, nullptr, 64, 64, 192, 0, 128, 0);
    k_edge_stats_part<<<dim3(64, 8), 256>>>();
    k_edge_stats_fin<<<1, 64>>>();
    k_edge_apply<<<dim3(16, 64, 4), 256>>>(g2, bb2, 64);

    // kNN round 2 on x2
    k_dist128<<<dim3(32, 32, 4), 256>>>(64);
    k_topk_part<<<512, 128>>>();
    k_topk_merge<<<64, 256>>>();

    // edge-conv 3 -> x3 (xcat[128:192))
    k_prepw<<<64, 64>>>(W3, p_Wc3);
    k_gemm128<<<dim3(32, 1, 4), 256>>>(p_AC, p_xcat, p_Wc3, nullptr, 64, 64, 192, 64, 128, 0);
    k_edge_stats_part<<<dim3(64, 8), 256>>>();
    k_edge_stats_fin<<<1, 64>>>();
    k_edge_apply<<<dim3(16, 64, 4), 256>>>(g3, bb3, 128);

    // global branch: y4 = W4 @ x3; fused stats+BN+lrelu+max -> gmax; fold into bias5
    k_gemm128<<<dim3(32, 4, 4), 256>>>(p_y4, p_xcat, W4, nullptr, 64, 64, 192, 128, 512, 0);
    k_stats_gmax<<<512, 256>>>(p_y4, g4, bb4);
    k_bias5<<<16, 128>>>(W5);

    // W5 on [x1;x2;x3] (C=192) + bias5; BN; lrelu
    k_gemm128<<<dim3(32, 4, 4), 256>>>(p_y5, p_xcat, W5, p_b5, 192, 704, 192, 0, 512, 0);
    k_statsapply<<<512, 256>>>(p_y5, 512, 0, g5, bb5);

    // W6
    k_gemm128<<<dim3(32, 2, 4), 256>>>(p_y6, p_y5, W6, nullptr, 512, 512, 512, 0, 256, 0);
    k_statsapply<<<256, 256>>>(p_y6, 256, 0, g6, bb6);

    // W7
    k_gemm128<<<dim3(32, 1, 4), 256>>>(p_y7, p_y6, W7, nullptr, 256, 256, 256, 0, 128, 0);
    k_statsapply<<<128, 256>>>(p_y7, 128, 0, g7, bb7);

    // final 128 -> 2
    k_final<<<dim3(16, 4), 256>>>(W8, b8, (float*)d_out);
}

// round 7
// speedup vs baseline: 1.7267x; 1.2287x over previous
#include <cuda_runtime.h>
#include <math.h>
#include <float.h>

#define Bsz 4
#define Npt 4096
#define KNN 20
#define EPSBN 1e-5f
#define NROWS (Bsz * Npt)
#define NGRP 512          // 8-col groups per row
#define KG 21             // groups kept (top-20 + 1 tie guard)

// ---------------- scratch (device globals; no allocations) ----------------
__device__ float d_dist[(size_t)Bsz * Npt * Npt];   // 268 MB distance matrix
__device__ float d_g8[(size_t)NROWS * NGRP];        // per-row 8-col group maxes
__device__ int   d_topg[NROWS * KG];                // top-21 group ids per row
__device__ float d_xcat[Bsz * 192 * Npt];           // x1|x2|x3 concatenated
__device__ float d_AC[Bsz * 128 * Npt];             // A (0:64) | Cc (64:128)
__device__ float d_y5[Bsz * 512 * Npt];
__device__ float d_y4[Bsz * 512 * Npt];
__device__ float d_y6[Bsz * 256 * Npt];
__device__ float d_y7[Bsz * 128 * Npt];
__device__ int   d_idx[Bsz * Npt * KNN];
__device__ float d_gmax[Bsz * 512];
__device__ float d_bias5[Bsz * 512];
__device__ float d_Wc2[128 * 64], d_Wc3[128 * 64];
__device__ float d_mean[64];
__device__ float d_rstd[64];
__device__ float d_espart[64 * 8 * 2];   // edge-stats partials (s, s2)

__device__ __forceinline__ float lrelu(float v) { return v >= 0.f ? v : 0.2f * v; }

// Kahan-compensated fp32 accumulator
__device__ __forceinline__ void kadd(float& s, float& c, float v) {
    float y = v - c;
    float t = s + y;
    c = (t - s) - y;
    s = t;
}

// register-resident sorted top-K insert (descending). Strict > keeps earlier insert on ties.
template <int K>
__device__ __forceinline__ void topk_insert(float (&tv)[K], int (&ti)[K], float v, int idx) {
    if (v > tv[K - 1]) {
        float cv = v; int ci = idx;
        #pragma unroll
        for (int t = 0; t < K; t++) {
            if (cv > tv[t]) {
                float x = tv[t]; int y = ti[t];
                tv[t] = cv; ti[t] = ci;
                cv = x; ci = y;
            }
        }
    }
}

// ---------------- conv1: 3 -> 64 ----------------
__global__ void k_conv1(const float* __restrict__ x, const float* __restrict__ W1) {
    int n = blockIdx.x * 256 + threadIdx.x;
    int o = blockIdx.y, b = blockIdx.z;
    float v = W1[o * 3 + 0] * x[(b * 3 + 0) * Npt + n]
            + W1[o * 3 + 1] * x[(b * 3 + 1) * Npt + n]
            + W1[o * 3 + 2] * x[(b * 3 + 2) * Npt + n];
    d_xcat[((long)b * 192 + o) * Npt + n] = v;
}

// ---------------- fused BN stats + apply + lrelu (in place, fp32 Kahan) ----------------
__global__ void k_statsapply(float* __restrict__ buf, int CT, int c0,
                             const float* __restrict__ gamma, const float* __restrict__ beta) {
    int o = blockIdx.x;
    float s = 0.f, sc = 0.f, s2 = 0.f, s2c = 0.f;
    for (int i = threadIdx.x; i < Bsz * Npt; i += 256) {
        int b = i >> 12, n = i & (Npt - 1);
        float v = buf[((long)b * CT + c0 + o) * Npt + n];
        kadd(s, sc, v);
        kadd(s2, s2c, v * v);
    }
    __shared__ float sh[256], sh2[256];
    __shared__ float smv, srv;
    sh[threadIdx.x] = s; sh2[threadIdx.x] = s2; __syncthreads();
    for (int st = 128; st > 0; st >>= 1) {
        if (threadIdx.x < st) { sh[threadIdx.x] += sh[threadIdx.x + st]; sh2[threadIdx.x] += sh2[threadIdx.x + st]; }
        __syncthreads();
    }
    if (threadIdx.x == 0) {
        float cnt = (float)(Bsz * Npt);
        float m = sh[0] / cnt;
        float var = sh2[0] / cnt - m * m;
        smv = m;
        srv = rsqrtf(fmaxf(var, 0.f) + EPSBN);
    }
    __syncthreads();
    float m = smv, r = srv, g = gamma[o], be = beta[o];
    for (int i = threadIdx.x; i < Bsz * Npt; i += 256) {
        int b = i >> 12, n = i & (Npt - 1);
        long off = ((long)b * CT + c0 + o) * Npt + n;
        buf[off] = lrelu((buf[off] - m) * r * g + be);
    }
}

// ======== 128x128 tile distance GEMM + per-thread 8-col group max ========
// writes 2*dot - sq[n] (row-constant sq[q] dropped: per-row order preserved)
__global__ void __launch_bounds__(256, 1) k_dist128(int c0) {
    __shared__ float Qs[16][132];
    __shared__ float Ms[16][128];
    __shared__ float sqM[128];
    int b = blockIdx.z, q0 = blockIdx.y * 128, n0 = blockIdx.x * 128;
    int tid = threadIdx.x, tx = tid & 15, ty = tid >> 4;
    float acc[2][2][4][4] = {};
    float myssq = 0.f;
    const float* xb = d_xcat + ((long)b * 192 + c0) * Npt;
    #pragma unroll 1
    for (int ck = 0; ck < 64; ck += 16) {
        #pragma unroll
        for (int r = 0; r < 8; r++) {
            int idx = r * 256 + tid;
            int cc = idx >> 7, e = idx & 127;
            long rowoff = (long)(ck + cc) * Npt;
            Qs[cc][e] = xb[rowoff + q0 + e];
            Ms[cc][e] = xb[rowoff + n0 + e];
        }
        __syncthreads();
        if (tid < 128) {
            #pragma unroll
            for (int cc = 0; cc < 16; cc++) {
                float v = Ms[cc][tid];
                myssq += v * v;
            }
        }
        #pragma unroll
        for (int k = 0; k < 16; k++) {
            float4 a0 = *(const float4*)&Qs[k][ty * 4];
            float4 a1 = *(const float4*)&Qs[k][64 + ty * 4];
            float4 b0 = *(const float4*)&Ms[k][tx * 4];
            float4 b1 = *(const float4*)&Ms[k][64 + tx * 4];
            float aa[2][4] = {{a0.x, a0.y, a0.z, a0.w}, {a1.x, a1.y, a1.z, a1.w}};
            float bb[2][4] = {{b0.x, b0.y, b0.z, b0.w}, {b1.x, b1.y, b1.z, b1.w}};
            #pragma unroll
            for (int ii = 0; ii < 2; ii++)
                #pragma unroll
                for (int i = 0; i < 4; i++)
                    #pragma unroll
                    for (int jj = 0; jj < 2; jj++)
                        #pragma unroll
                        for (int j = 0; j < 4; j++)
                            acc[ii][jj][i][j] += aa[ii][i] * bb[jj][j];
        }
        __syncthreads();
    }
    if (tid < 128) sqM[tid] = myssq;
    __syncthreads();
    long bN = (long)b * Npt;
    float sn0[4], sn1[4];
    #pragma unroll
    for (int j = 0; j < 4; j++) {
        sn0[j] = sqM[tx * 4 + j];
        sn1[j] = sqM[64 + tx * 4 + j];
    }
    #pragma unroll
    for (int ii = 0; ii < 2; ii++) {
        #pragma unroll
        for (int i = 0; i < 4; i++) {
            int q = q0 + ii * 64 + ty * 4 + i;
            float* row = d_dist + (bN + q) * Npt + n0;
            float4 v0, v1;
            v0.x = 2.f * acc[ii][0][i][0] - sn0[0];
            v0.y = 2.f * acc[ii][0][i][1] - sn0[1];
            v0.z = 2.f * acc[ii][0][i][2] - sn0[2];
            v0.w = 2.f * acc[ii][0][i][3] - sn0[3];
            v1.x = 2.f * acc[ii][1][i][0] - sn1[0];
            v1.y = 2.f * acc[ii][1][i][1] - sn1[1];
            v1.z = 2.f * acc[ii][1][i][2] - sn1[2];
            v1.w = 2.f * acc[ii][1][i][3] - sn1[3];
            *(float4*)&row[tx * 4] = v0;
            *(float4*)&row[64 + tx * 4] = v1;
            // 8-col group max (group id = blockIdx.x*16 + tx)
            float m01 = fmaxf(fmaxf(v0.x, v0.y), fmaxf(v0.z, v0.w));
            float m23 = fmaxf(fmaxf(v1.x, v1.y), fmaxf(v1.z, v1.w));
            d_g8[(bN + q) * NGRP + blockIdx.x * 16 + tx] = fmaxf(m01, m23);
        }
    }
}

// ---------------- select top-21 groups per row (warp = 32 rows over 512 groups) ----------------
__global__ void k_groupsel() {
    __shared__ float sh[8][32][33];
    int warp = threadIdx.x >> 5, lane = threadIdx.x & 31;
    int rowBase = (blockIdx.x * 8 + warp) * 32;
    float tv[KG]; int ti[KG];
    #pragma unroll
    for (int t = 0; t < KG; t++) { tv[t] = -FLT_MAX; ti[t] = 0; }
    for (int g0 = 0; g0 < NGRP; g0 += 32) {
        #pragma unroll 8
        for (int rr = 0; rr < 32; rr++)
            sh[warp][rr][lane] = d_g8[((long)(rowBase + rr)) * NGRP + g0 + lane];
        __syncwarp();
        #pragma unroll 4
        for (int j = 0; j < 32; j++)
            topk_insert<KG>(tv, ti, sh[warp][lane][j], g0 + j);
        __syncwarp();
    }
    int row = rowBase + lane;
    #pragma unroll
    for (int t = 0; t < KG; t++) d_topg[row * KG + t] = ti[t];
}

// ---------------- gather 21 groups (168 candidates) and exact top-20 with indices ----------------
__global__ void k_gather_topk() {
    int row = blockIdx.x * 256 + threadIdx.x;   // one thread per row
    const float* drow = d_dist + (long)row * Npt;
    float tv[KNN]; int ti[KNN];
    #pragma unroll
    for (int t = 0; t < KNN; t++) { tv[t] = -FLT_MAX; ti[t] = 0; }
    #pragma unroll 1
    for (int t = 0; t < KG; t++) {
        int g = d_topg[row * KG + t];
        int base = (g >> 4) * 128 + (g & 15) * 4;
        float4 a = *(const float4*)&drow[base];
        float4 bb = *(const float4*)&drow[base + 64];
        topk_insert<KNN>(tv, ti, a.x,  base + 0);
        topk_insert<KNN>(tv, ti, a.y,  base + 1);
        topk_insert<KNN>(tv, ti, a.z,  base + 2);
        topk_insert<KNN>(tv, ti, a.w,  base + 3);
        topk_insert<KNN>(tv, ti, bb.x, base + 64);
        topk_insert<KNN>(tv, ti, bb.y, base + 65);
        topk_insert<KNN>(tv, ti, bb.z, base + 66);
        topk_insert<KNN>(tv, ti, bb.w, base + 67);
    }
    #pragma unroll
    for (int t = 0; t < KNN; t++) d_idx[row * KNN + t] = ti[t];
}

// ---------------- combined weight prep ----------------
__global__ void k_prepw(const float* __restrict__ W, float* __restrict__ Wc) {
    int o = blockIdx.x, c = threadIdx.x;
    float a = W[o * 128 + c], bb = W[o * 128 + 64 + c];
    Wc[o * 64 + c] = a;
    Wc[(64 + o) * 64 + c] = bb - a;
}

// ======== 128x128 tile feature GEMM ========
__global__ void __launch_bounds__(256, 1) k_gemm128(
        float* __restrict__ out, const float* __restrict__ in,
        const float* __restrict__ W, const float* __restrict__ biasBO,
        int C, int ldw, int CTin, int c0in, int CTout, int c0out) {
    __shared__ float Ws[16][132];
    __shared__ float Xs[16][128];
    int b = blockIdx.z, o0 = blockIdx.y * 128, n0 = blockIdx.x * 128;
    int tid = threadIdx.x, tx = tid & 15, ty = tid >> 4;
    float acc[2][2][4][4] = {};
    const float* inB = in + ((long)b * CTin + c0in) * Npt + n0;
    #pragma unroll 1
    for (int ck = 0; ck < C; ck += 16) {
        #pragma unroll
        for (int r = 0; r < 8; r++) {
            int idx = r * 256 + tid;
            int oo = idx >> 4, cc = idx & 15;
            Ws[cc][oo] = W[(long)(o0 + oo) * ldw + ck + cc];
        }
        #pragma unroll
        for (int r = 0; r < 8; r++) {
            int idx = r * 256 + tid;
            int cc = idx >> 7, e = idx & 127;
            Xs[cc][e] = inB[(long)(ck + cc) * Npt + e];
        }
        __syncthreads();
        #pragma unroll
        for (int k = 0; k < 16; k++) {
            float4 a0 = *(const float4*)&Ws[k][ty * 4];
            float4 a1 = *(const float4*)&Ws[k][64 + ty * 4];
            float4 b0 = *(const float4*)&Xs[k][tx * 4];
            float4 b1 = *(const float4*)&Xs[k][64 + tx * 4];
            float aa[2][4] = {{a0.x, a0.y, a0.z, a0.w}, {a1.x, a1.y, a1.z, a1.w}};
            float bb[2][4] = {{b0.x, b0.y, b0.z, b0.w}, {b1.x, b1.y, b1.z, b1.w}};
            #pragma unroll
            for (int ii = 0; ii < 2; ii++)
                #pragma unroll
                for (int i = 0; i < 4; i++)
                    #pragma unroll
                    for (int jj = 0; jj < 2; jj++)
                        #pragma unroll
                        for (int j = 0; j < 4; j++)
                            acc[ii][jj][i][j] += aa[ii][i] * bb[jj][j];
        }
        __syncthreads();
    }
    #pragma unroll
    for (int ii = 0; ii < 2; ii++) {
        #pragma unroll
        for (int i = 0; i < 4; i++) {
            int o = o0 + ii * 64 + ty * 4 + i;
            float bias = biasBO ? biasBO[b * 512 + o] : 0.f;
            float* row = out + ((long)b * CTout + c0out + o) * Npt + n0;
            float4 v0, v1;
            v0.x = acc[ii][0][i][0] + bias; v0.y = acc[ii][0][i][1] + bias;
            v0.z = acc[ii][0][i][2] + bias; v0.w = acc[ii][0][i][3] + bias;
            v1.x = acc[ii][1][i][0] + bias; v1.y = acc[ii][1][i][1] + bias;
            v1.z = acc[ii][1][i][2] + bias; v1.w = acc[ii][1][i][3] + bias;
            *(float4*)&row[tx * 4] = v0;
            *(float4*)&row[64 + tx * 4] = v1;
        }
    }
}

// ---------------- edge-conv BN stats: stage 1 (64 channels x 8 slices) ----------------
__global__ void k_edge_stats_part() {
    int o = blockIdx.x, slice = blockIdx.y;
    int tid = threadIdx.x;
    float s = 0.f, sc = 0.f, s2 = 0.f, s2c = 0.f;
    #pragma unroll 1
    for (int b = 0; b < Bsz; b++) {
        const float* Ab = d_AC + ((long)b * 128 + o) * Npt;
        const float* Cb = d_AC + ((long)b * 128 + 64 + o) * Npt;
        #pragma unroll 1
        for (int n = slice * 512 + tid; n < (slice + 1) * 512; n += 256) {
            float cc = Cb[n];
            const int* ip = d_idx + ((long)(b * Npt + n)) * KNN;
            #pragma unroll 4
            for (int k = 0; k < KNN; k++) {
                float v = Ab[ip[k]] + cc;
                kadd(s, sc, v);
                kadd(s2, s2c, v * v);
            }
        }
    }
    __shared__ float sh[256], sh2[256];
    sh[tid] = s; sh2[tid] = s2; __syncthreads();
    for (int st = 128; st > 0; st >>= 1) {
        if (tid < st) { sh[tid] += sh[tid + st]; sh2[tid] += sh2[tid + st]; }
        __syncthreads();
    }
    if (tid == 0) {
        d_espart[(o * 8 + slice) * 2 + 0] = sh[0];
        d_espart[(o * 8 + slice) * 2 + 1] = sh2[0];
    }
}

// ---------------- edge-conv BN stats: finalize ----------------
__global__ void k_edge_stats_fin() {
    int o = threadIdx.x;  // 64
    float s = 0.f, s2 = 0.f;
    #pragma unroll
    for (int p = 0; p < 8; p++) {
        s += d_espart[(o * 8 + p) * 2 + 0];
        s2 += d_espart[(o * 8 + p) * 2 + 1];
    }
    float cnt = (float)(Bsz * Npt * KNN);
    float m = s / cnt;
    float var = s2 / cnt - m * m;
    d_mean[o] = m;
    d_rstd[o] = rsqrtf(fmaxf(var, 0.f) + EPSBN);
}

// ---------------- edge-conv BN+lrelu+max_k ----------------
__global__ void k_edge_apply(const float* __restrict__ gamma, const float* __restrict__ beta, int c0out) {
    int n = blockIdx.x * 256 + threadIdx.x, o = blockIdx.y, b = blockIdx.z;
    float m = d_mean[o], r = d_rstd[o], g = gamma[o], be = beta[o];
    const float* Ab = d_AC + ((long)b * 128 + o) * Npt;
    float cc = d_AC[((long)b * 128 + 64 + o) * Npt + n];
    const int* ip = d_idx + (b * Npt + n) * KNN;
    float best = -FLT_MAX;
    #pragma unroll 4
    for (int k = 0; k < KNN; k++) {
        float v = Ab[ip[k]] + cc;
        v = lrelu((v - m) * r * g + be);
        best = fmaxf(best, v);
    }
    d_xcat[((long)b * 192 + c0out + o) * Npt + n] = best;
}

// ---------------- fused stats + BN + lrelu + max over n -> gmax (fp32 Kahan) ----------------
__global__ void k_stats_gmax(const float* __restrict__ buf,
                             const float* __restrict__ gamma, const float* __restrict__ beta) {
    int o = blockIdx.x;  // 512
    float s = 0.f, sc = 0.f, s2 = 0.f, s2c = 0.f;
    for (int i = threadIdx.x; i < Bsz * Npt; i += 256) {
        int b = i >> 12, n = i & (Npt - 1);
        float v = buf[((long)b * 512 + o) * Npt + n];
        kadd(s, sc, v);
        kadd(s2, s2c, v * v);
    }
    __shared__ float sh[256], sh2[256];
    __shared__ float smv, srv;
    sh[threadIdx.x] = s; sh2[threadIdx.x] = s2; __syncthreads();
    for (int st = 128; st > 0; st >>= 1) {
        if (threadIdx.x < st) { sh[threadIdx.x] += sh[threadIdx.x + st]; sh2[threadIdx.x] += sh2[threadIdx.x + st]; }
        __syncthreads();
    }
    if (threadIdx.x == 0) {
        float cnt = (float)(Bsz * Npt);
        float m = sh[0] / cnt;
        float var = sh2[0] / cnt - m * m;
        smv = m;
        srv = rsqrtf(fmaxf(var, 0.f) + EPSBN);
    }
    __syncthreads();
    float m = smv, r = srv, g = gamma[o], be = beta[o];
    __shared__ float shm[256];
    for (int b = 0; b < Bsz; b++) {
        float best = -FLT_MAX;
        for (int n = threadIdx.x; n < Npt; n += 256) {
            float v = buf[((long)b * 512 + o) * Npt + n];
            best = fmaxf(best, lrelu((v - m) * r * g + be));
        }
        shm[threadIdx.x] = best; __syncthreads();
        for (int st = 128; st > 0; st >>= 1) {
            if (threadIdx.x < st) shm[threadIdx.x] = fmaxf(shm[threadIdx.x], shm[threadIdx.x + st]);
            __syncthreads();
        }
        if (threadIdx.x == 0) d_gmax[b * 512 + o] = shm[0];
        __syncthreads();
    }
}

// ---------------- fold W5[:,192:] @ broadcast(gmax) into a per-(b,o) bias ----------------
__global__ void k_bias5(const float* __restrict__ W5) {
    int t = blockIdx.x * 128 + threadIdx.x;
    int b = t >> 9, o = t & 511;
    float s = 0.f;
    #pragma unroll 8
    for (int c = 0; c < 512; c++)
        s += W5[(long)o * 704 + 192 + c] * d_gmax[b * 512 + c];
    d_bias5[b * 512 + o] = s;
}

// ---------------- final conv 128 -> 2 + bias ----------------
__global__ void k_final(const float* __restrict__ W8, const float* __restrict__ b8,
                        float* __restrict__ out) {
    int n = blockIdx.x * 256 + threadIdx.x, b = blockIdx.y;
    float s0 = b8[0], s1 = b8[1];
    #pragma unroll 8
    for (int c = 0; c < 128; c++) {
        float h = d_y7[((long)b * 128 + c) * Npt + n];
        s0 += W8[c] * h;
        s1 += W8[128 + c] * h;
    }
    out[(b * 2 + 0) * Npt + n] = s0;
    out[(b * 2 + 1) * Npt + n] = s1;
}

// ---------------- host ----------------
extern "C" void kernel_launch(void* const* d_in, const int* in_sizes, int n_in,
                              void* d_out, int out_size) {
    (void)in_sizes; (void)n_in; (void)out_size;
    const float* x   = (const float*)d_in[0];
    const float* W1  = (const float*)d_in[1];
    const float* W2  = (const float*)d_in[2];
    const float* W3  = (const float*)d_in[3];
    const float* W4  = (const float*)d_in[4];
    const float* W5  = (const float*)d_in[5];
    const float* W6  = (const float*)d_in[6];
    const float* W7  = (const float*)d_in[7];
    const float* W8  = (const float*)d_in[8];
    const float* b8  = (const float*)d_in[9];
    const float* g1 = (const float*)d_in[10], *bb1 = (const float*)d_in[11];
    const float* g2 = (const float*)d_in[12], *bb2 = (const float*)d_in[13];
    const float* g3 = (const float*)d_in[14], *bb3 = (const float*)d_in[15];
    const float* g4 = (const float*)d_in[16], *bb4 = (const float*)d_in[17];
    const float* g5 = (const float*)d_in[18], *bb5 = (const float*)d_in[19];
    const float* g6 = (const float*)d_in[20], *bb6 = (const float*)d_in[21];
    const float* g7 = (const float*)d_in[22], *bb7 = (const float*)d_in[23];

    void *pv;
    cudaGetSymbolAddress(&pv, d_xcat);  float* p_xcat = (float*)pv;
    cudaGetSymbolAddress(&pv, d_AC);    float* p_AC   = (float*)pv;
    cudaGetSymbolAddress(&pv, d_y4);    float* p_y4   = (float*)pv;
    cudaGetSymbolAddress(&pv, d_y5);    float* p_y5   = (float*)pv;
    cudaGetSymbolAddress(&pv, d_y6);    float* p_y6   = (float*)pv;
    cudaGetSymbolAddress(&pv, d_y7);    float* p_y7   = (float*)pv;
    cudaGetSymbolAddress(&pv, d_bias5); float* p_b5   = (float*)pv;
    cudaGetSymbolAddress(&pv, d_Wc2);   float* p_Wc2  = (float*)pv;
    cudaGetSymbolAddress(&pv, d_Wc3);   float* p_Wc3  = (float*)pv;

    // conv1 + BN + lrelu -> x1 (xcat[0:64))
    k_conv1<<<dim3(16, 64, 4), 256>>>(x, W1);
    k_statsapply<<<64, 256>>>(p_xcat, 192, 0, g1, bb1);

    // kNN round 1 on x1: dist + group max -> top-21 groups -> exact top-20
    k_dist128<<<dim3(32, 32, 4), 256>>>(0);
    k_groupsel<<<64, 256>>>();
    k_gather_topk<<<64, 256>>>();

    // edge-conv 2 -> x2 (xcat[64:128))
    k_prepw<<<64, 64>>>(W2, p_Wc2);
    k_gemm128<<<dim3(32, 1, 4), 256>>>(p_AC, p_xcat, p_Wc2, nullptr, 64, 64, 192, 0, 128, 0);
    k_edge_stats_part<<<dim3(64, 8), 256>>>();
    k_edge_stats_fin<<<1, 64>>>();
    k_edge_apply<<<dim3(16, 64, 4), 256>>>(g2, bb2, 64);

    // kNN round 2 on x2
    k_dist128<<<dim3(32, 32, 4), 256>>>(64);
    k_groupsel<<<64, 256>>>();
    k_gather_topk<<<64, 256>>>();

    // edge-conv 3 -> x3 (xcat[128:192))
    k_prepw<<<64, 64>>>(W3, p_Wc3);
    k_gemm128<<<dim3(32, 1, 4), 256>>>(p_AC, p_xcat, p_Wc3, nullptr, 64, 64, 192, 64, 128, 0);
    k_edge_stats_part<<<dim3(64, 8), 256>>>();
    k_edge_stats_fin<<<1, 64>>>();
    k_edge_apply<<<dim3(16, 64, 4), 256>>>(g3, bb3, 128);

    // global branch: y4 = W4 @ x3; fused stats+BN+lrelu+max -> gmax; fold into bias5
    k_gemm128<<<dim3(32, 4, 4), 256>>>(p_y4, p_xcat, W4, nullptr, 64, 64, 192, 128, 512, 0);
    k_stats_gmax<<<512, 256>>>(p_y4, g4, bb4);
    k_bias5<<<16, 128>>>(W5);

    // W5 on [x1;x2;x3] (C=192) + bias5; BN; lrelu
    k_gemm128<<<dim3(32, 4, 4), 256>>>(p_y5, p_xcat, W5, p_b5, 192, 704, 192, 0, 512, 0);
    k_statsapply<<<512, 256>>>(p_y5, 512, 0, g5, bb5);

    // W6
    k_gemm128<<<dim3(32, 2, 4), 256>>>(p_y6, p_y5, W6, nullptr, 512, 512, 512, 0, 256, 0);
    k_statsapply<<<256, 256>>>(p_y6, 256, 0, g6, bb6);

    // W7
    k_gemm128<<<dim3(32, 1, 4), 256>>>(p_y7, p_y6, W7, nullptr, 256, 256, 256, 0, 128, 0);
    k_statsapply<<<128, 256>>>(p_y7, 128, 0, g7, bb7);

    // final 128 -> 2
    k_final<<<dim3(16, 4), 256>>>(W8, b8, (float*)d_out);
}

// round 8
// speedup vs baseline: 2.1923x; 1.2697x over previous
#include <cuda_runtime.h>
#include <math.h>
#include <float.h>

#define Bsz 4
#define Npt 4096
#define KNN 20
#define EPSBN 1e-5f
#define NROWS (Bsz * Npt)
#define NGRP 512          // 8-col groups per row
#define KG 21             // groups kept (top-20 + 1 tie guard)

// ---------------- scratch (device globals; no allocations) ----------------
__device__ float d_dist[(size_t)Bsz * Npt * Npt];   // 268 MB distance matrix
__device__ float d_g8[(size_t)NROWS * NGRP];        // per-row 8-col group maxes
__device__ int   d_topg[NROWS * KG];                // top-21 group ids per row
__device__ float d_xcat[Bsz * 192 * Npt];           // x1|x2|x3 concatenated
__device__ float d_AC[Bsz * 128 * Npt];             // A (0:64) | Cc (64:128)
__device__ float d_y5[Bsz * 512 * Npt];
__device__ float d_y4[Bsz * 512 * Npt];
__device__ float d_y6[Bsz * 256 * Npt];
__device__ float d_y7[Bsz * 128 * Npt];
__device__ int   d_idx[Bsz * Npt * KNN];
__device__ float d_gmax[Bsz * 512];
__device__ float d_bias5[Bsz * 512];
__device__ float d_Wc2[128 * 64], d_Wc3[128 * 64];
__device__ float d_mean[64];
__device__ float d_rstd[64];
__device__ float d_espart[64 * 8 * 2];   // edge-stats partials (s, s2)

__device__ __forceinline__ float lrelu(float v) { return v >= 0.f ? v : 0.2f * v; }

// Kahan-compensated fp32 accumulator
__device__ __forceinline__ void kadd(float& s, float& c, float v) {
    float y = v - c;
    float t = s + y;
    c = (t - s) - y;
    s = t;
}

// ---------------- conv1: 3 -> 64 ----------------
__global__ void k_conv1(const float* __restrict__ x, const float* __restrict__ W1) {
    int n = blockIdx.x * 256 + threadIdx.x;
    int o = blockIdx.y, b = blockIdx.z;
    float v = W1[o * 3 + 0] * x[(b * 3 + 0) * Npt + n]
            + W1[o * 3 + 1] * x[(b * 3 + 1) * Npt + n]
            + W1[o * 3 + 2] * x[(b * 3 + 2) * Npt + n];
    d_xcat[((long)b * 192 + o) * Npt + n] = v;
}

// ---------------- fused BN stats + apply + lrelu (in place, fp32 Kahan) ----------------
__global__ void k_statsapply(float* __restrict__ buf, int CT, int c0,
                             const float* __restrict__ gamma, const float* __restrict__ beta) {
    int o = blockIdx.x;
    float s = 0.f, sc = 0.f, s2 = 0.f, s2c = 0.f;
    for (int i = threadIdx.x; i < Bsz * Npt; i += 256) {
        int b = i >> 12, n = i & (Npt - 1);
        float v = buf[((long)b * CT + c0 + o) * Npt + n];
        kadd(s, sc, v);
        kadd(s2, s2c, v * v);
    }
    __shared__ float sh[256], sh2[256];
    __shared__ float smv, srv;
    sh[threadIdx.x] = s; sh2[threadIdx.x] = s2; __syncthreads();
    for (int st = 128; st > 0; st >>= 1) {
        if (threadIdx.x < st) { sh[threadIdx.x] += sh[threadIdx.x + st]; sh2[threadIdx.x] += sh2[threadIdx.x + st]; }
        __syncthreads();
    }
    if (threadIdx.x == 0) {
        float cnt = (float)(Bsz * Npt);
        float m = sh[0] / cnt;
        float var = sh2[0] / cnt - m * m;
        smv = m;
        srv = rsqrtf(fmaxf(var, 0.f) + EPSBN);
    }
    __syncthreads();
    float m = smv, r = srv, g = gamma[o], be = beta[o];
    for (int i = threadIdx.x; i < Bsz * Npt; i += 256) {
        int b = i >> 12, n = i & (Npt - 1);
        long off = ((long)b * CT + c0 + o) * Npt + n;
        buf[off] = lrelu((buf[off] - m) * r * g + be);
    }
}

// ======== 128x128 tile distance GEMM + per-thread 8-col group max ========
// writes 2*dot - sq[n] (row-constant sq[q] dropped: per-row order preserved)
__global__ void __launch_bounds__(256, 1) k_dist128(int c0) {
    __shared__ float Qs[16][132];
    __shared__ float Ms[16][128];
    __shared__ float sqM[128];
    int b = blockIdx.z, q0 = blockIdx.y * 128, n0 = blockIdx.x * 128;
    int tid = threadIdx.x, tx = tid & 15, ty = tid >> 4;
    float acc[2][2][4][4] = {};
    float myssq = 0.f;
    const float* xb = d_xcat + ((long)b * 192 + c0) * Npt;
    #pragma unroll 1
    for (int ck = 0; ck < 64; ck += 16) {
        #pragma unroll
        for (int r = 0; r < 8; r++) {
            int idx = r * 256 + tid;
            int cc = idx >> 7, e = idx & 127;
            long rowoff = (long)(ck + cc) * Npt;
            Qs[cc][e] = xb[rowoff + q0 + e];
            Ms[cc][e] = xb[rowoff + n0 + e];
        }
        __syncthreads();
        if (tid < 128) {
            #pragma unroll
            for (int cc = 0; cc < 16; cc++) {
                float v = Ms[cc][tid];
                myssq += v * v;
            }
        }
        #pragma unroll
        for (int k = 0; k < 16; k++) {
            float4 a0 = *(const float4*)&Qs[k][ty * 4];
            float4 a1 = *(const float4*)&Qs[k][64 + ty * 4];
            float4 b0 = *(const float4*)&Ms[k][tx * 4];
            float4 b1 = *(const float4*)&Ms[k][64 + tx * 4];
            float aa[2][4] = {{a0.x, a0.y, a0.z, a0.w}, {a1.x, a1.y, a1.z, a1.w}};
            float bb[2][4] = {{b0.x, b0.y, b0.z, b0.w}, {b1.x, b1.y, b1.z, b1.w}};
            #pragma unroll
            for (int ii = 0; ii < 2; ii++)
                #pragma unroll
                for (int i = 0; i < 4; i++)
                    #pragma unroll
                    for (int jj = 0; jj < 2; jj++)
                        #pragma unroll
                        for (int j = 0; j < 4; j++)
                            acc[ii][jj][i][j] += aa[ii][i] * bb[jj][j];
        }
        __syncthreads();
    }
    if (tid < 128) sqM[tid] = myssq;
    __syncthreads();
    long bN = (long)b * Npt;
    float sn0[4], sn1[4];
    #pragma unroll
    for (int j = 0; j < 4; j++) {
        sn0[j] = sqM[tx * 4 + j];
        sn1[j] = sqM[64 + tx * 4 + j];
    }
    #pragma unroll
    for (int ii = 0; ii < 2; ii++) {
        #pragma unroll
        for (int i = 0; i < 4; i++) {
            int q = q0 + ii * 64 + ty * 4 + i;
            float* row = d_dist + (bN + q) * Npt + n0;
            float4 v0, v1;
            v0.x = 2.f * acc[ii][0][i][0] - sn0[0];
            v0.y = 2.f * acc[ii][0][i][1] - sn0[1];
            v0.z = 2.f * acc[ii][0][i][2] - sn0[2];
            v0.w = 2.f * acc[ii][0][i][3] - sn0[3];
            v1.x = 2.f * acc[ii][1][i][0] - sn1[0];
            v1.y = 2.f * acc[ii][1][i][1] - sn1[1];
            v1.z = 2.f * acc[ii][1][i][2] - sn1[2];
            v1.w = 2.f * acc[ii][1][i][3] - sn1[3];
            *(float4*)&row[tx * 4] = v0;
            *(float4*)&row[64 + tx * 4] = v1;
            // 8-col group max (group id = blockIdx.x*16 + tx)
            float m01 = fmaxf(fmaxf(v0.x, v0.y), fmaxf(v0.z, v0.w));
            float m23 = fmaxf(fmaxf(v1.x, v1.y), fmaxf(v1.z, v1.w));
            d_g8[(bN + q) * NGRP + blockIdx.x * 16 + tx] = fmaxf(m01, m23);
        }
    }
}

// ---------------- warp-per-row top-21 group selection (iterative warp argmax) ----------------
__global__ void k_groupsel() {
    int warp = threadIdx.x >> 5, lane = threadIdx.x & 31;
    int row = blockIdx.x * 8 + warp;
    const float* g = d_g8 + (long)row * NGRP;
    float v[16];
    #pragma unroll
    for (int j = 0; j < 16; j++) v[j] = g[lane + 32 * j];
    // local max
    float lmax = v[0]; int lj = 0;
    #pragma unroll
    for (int j = 1; j < 16; j++) if (v[j] > lmax) { lmax = v[j]; lj = j; }
    #pragma unroll 1
    for (int t = 0; t < KG; t++) {
        float bv = lmax; int bidx = lane + 32 * lj;
        #pragma unroll
        for (int off = 16; off > 0; off >>= 1) {
            float ov = __shfl_xor_sync(0xffffffffu, bv, off);
            int oi = __shfl_xor_sync(0xffffffffu, bidx, off);
            if (ov > bv || (ov == bv && oi < bidx)) { bv = ov; bidx = oi; }
        }
        if (lane == 0) d_topg[row * KG + t] = bidx;
        if ((bidx & 31) == lane) {
            int s = bidx >> 5;
            #pragma unroll
            for (int j = 0; j < 16; j++) if (j == s) v[j] = -FLT_MAX;
            lmax = v[0]; lj = 0;
            #pragma unroll
            for (int j = 1; j < 16; j++) if (v[j] > lmax) { lmax = v[j]; lj = j; }
        }
    }
}

// ---------------- warp-per-row exact top-20 over the 21 selected groups ----------------
__global__ void k_gather_topk() {
    int warp = threadIdx.x >> 5, lane = threadIdx.x & 31;
    int row = blockIdx.x * 8 + warp;
    const float* drow = d_dist + (long)row * Npt;
    float v[8];
    int base = 0;
    if (lane < KG) {
        int g = d_topg[row * KG + lane];
        base = (g >> 4) * 128 + (g & 15) * 4;
        float4 a = *(const float4*)&drow[base];
        float4 bb = *(const float4*)&drow[base + 64];
        v[0] = a.x;  v[1] = a.y;  v[2] = a.z;  v[3] = a.w;
        v[4] = bb.x; v[5] = bb.y; v[6] = bb.z; v[7] = bb.w;
    } else {
        #pragma unroll
        for (int j = 0; j < 8; j++) v[j] = -FLT_MAX;
    }
    // element index for slot j: j<4 -> base+j ; j>=4 -> base+60+j
    float lmax = v[0]; int lj = 0;
    #pragma unroll
    for (int j = 1; j < 8; j++) if (v[j] > lmax) { lmax = v[j]; lj = j; }
    #pragma unroll 1
    for (int t = 0; t < KNN; t++) {
        int lidx = base + (lj < 4 ? lj : 60 + lj);
        float bv = lmax; int bidx = lidx;
        #pragma unroll
        for (int off = 16; off > 0; off >>= 1) {
            float ov = __shfl_xor_sync(0xffffffffu, bv, off);
            int oi = __shfl_xor_sync(0xffffffffu, bidx, off);
            if (ov > bv || (ov == bv && oi < bidx)) { bv = ov; bidx = oi; }
        }
        if (lane == 0) d_idx[row * KNN + t] = bidx;
        if (bv == lmax && bidx == lidx) {
            #pragma unroll
            for (int j = 0; j < 8; j++) if (j == lj) v[j] = -FLT_MAX;
            lmax = v[0]; lj = 0;
            #pragma unroll
            for (int j = 1; j < 8; j++) if (v[j] > lmax) { lmax = v[j]; lj = j; }
        }
    }
}

// ---------------- combined weight prep ----------------
__global__ void k_prepw(const float* __restrict__ W, float* __restrict__ Wc) {
    int o = blockIdx.x, c = threadIdx.x;
    float a = W[o * 128 + c], bb = W[o * 128 + 64 + c];
    Wc[o * 64 + c] = a;
    Wc[(64 + o) * 64 + c] = bb - a;
}

// ======== 128x128 tile feature GEMM ========
__global__ void __launch_bounds__(256, 1) k_gemm128(
        float* __restrict__ out, const float* __restrict__ in,
        const float* __restrict__ W, const float* __restrict__ biasBO,
        int C, int ldw, int CTin, int c0in, int CTout, int c0out) {
    __shared__ float Ws[16][132];
    __shared__ float Xs[16][128];
    int b = blockIdx.z, o0 = blockIdx.y * 128, n0 = blockIdx.x * 128;
    int tid = threadIdx.x, tx = tid & 15, ty = tid >> 4;
    float acc[2][2][4][4] = {};
    const float* inB = in + ((long)b * CTin + c0in) * Npt + n0;
    #pragma unroll 1
    for (int ck = 0; ck < C; ck += 16) {
        #pragma unroll
        for (int r = 0; r < 8; r++) {
            int idx = r * 256 + tid;
            int oo = idx >> 4, cc = idx & 15;
            Ws[cc][oo] = W[(long)(o0 + oo) * ldw + ck + cc];
        }
        #pragma unroll
        for (int r = 0; r < 8; r++) {
            int idx = r * 256 + tid;
            int cc = idx >> 7, e = idx & 127;
            Xs[cc][e] = inB[(long)(ck + cc) * Npt + e];
        }
        __syncthreads();
        #pragma unroll
        for (int k = 0; k < 16; k++) {
            float4 a0 = *(const float4*)&Ws[k][ty * 4];
            float4 a1 = *(const float4*)&Ws[k][64 + ty * 4];
            float4 b0 = *(const float4*)&Xs[k][tx * 4];
            float4 b1 = *(const float4*)&Xs[k][64 + tx * 4];
            float aa[2][4] = {{a0.x, a0.y, a0.z, a0.w}, {a1.x, a1.y, a1.z, a1.w}};
            float bb[2][4] = {{b0.x, b0.y, b0.z, b0.w}, {b1.x, b1.y, b1.z, b1.w}};
            #pragma unroll
            for (int ii = 0; ii < 2; ii++)
                #pragma unroll
                for (int i = 0; i < 4; i++)
                    #pragma unroll
                    for (int jj = 0; jj < 2; jj++)
                        #pragma unroll
                        for (int j = 0; j < 4; j++)
                            acc[ii][jj][i][j] += aa[ii][i] * bb[jj][j];
        }
        __syncthreads();
    }
    #pragma unroll
    for (int ii = 0; ii < 2; ii++) {
        #pragma unroll
        for (int i = 0; i < 4; i++) {
            int o = o0 + ii * 64 + ty * 4 + i;
            float bias = biasBO ? biasBO[b * 512 + o] : 0.f;
            float* row = out + ((long)b * CTout + c0out + o) * Npt + n0;
            float4 v0, v1;
            v0.x = acc[ii][0][i][0] + bias; v0.y = acc[ii][0][i][1] + bias;
            v0.z = acc[ii][0][i][2] + bias; v0.w = acc[ii][0][i][3] + bias;
            v1.x = acc[ii][1][i][0] + bias; v1.y = acc[ii][1][i][1] + bias;
            v1.z = acc[ii][1][i][2] + bias; v1.w = acc[ii][1][i][3] + bias;
            *(float4*)&row[tx * 4] = v0;
            *(float4*)&row[64 + tx * 4] = v1;
        }
    }
}

// ---------------- edge-conv BN stats: stage 1 (64 channels x 8 slices) ----------------
__global__ void k_edge_stats_part() {
    int o = blockIdx.x, slice = blockIdx.y;
    int tid = threadIdx.x;
    float s = 0.f, sc = 0.f, s2 = 0.f, s2c = 0.f;
    #pragma unroll 1
    for (int b = 0; b < Bsz; b++) {
        const float* Ab = d_AC + ((long)b * 128 + o) * Npt;
        const float* Cb = d_AC + ((long)b * 128 + 64 + o) * Npt;
        #pragma unroll 1
        for (int n = slice * 512 + tid; n < (slice + 1) * 512; n += 256) {
            float cc = Cb[n];
            const int* ip = d_idx + ((long)(b * Npt + n)) * KNN;
            #pragma unroll 4
            for (int k = 0; k < KNN; k++) {
                float v = Ab[ip[k]] + cc;
                kadd(s, sc, v);
                kadd(s2, s2c, v * v);
            }
        }
    }
    __shared__ float sh[256], sh2[256];
    sh[tid] = s; sh2[tid] = s2; __syncthreads();
    for (int st = 128; st > 0; st >>= 1) {
        if (tid < st) { sh[tid] += sh[tid + st]; sh2[tid] += sh2[tid + st]; }
        __syncthreads();
    }
    if (tid == 0) {
        d_espart[(o * 8 + slice) * 2 + 0] = sh[0];
        d_espart[(o * 8 + slice) * 2 + 1] = sh2[0];
    }
}

// ---------------- edge-conv BN stats: finalize ----------------
__global__ void k_edge_stats_fin() {
    int o = threadIdx.x;  // 64
    float s = 0.f, s2 = 0.f;
    #pragma unroll
    for (int p = 0; p < 8; p++) {
        s += d_espart[(o * 8 + p) * 2 + 0];
        s2 += d_espart[(o * 8 + p) * 2 + 1];
    }
    float cnt = (float)(Bsz * Npt * KNN);
    float m = s / cnt;
    float var = s2 / cnt - m * m;
    d_mean[o] = m;
    d_rstd[o] = rsqrtf(fmaxf(var, 0.f) + EPSBN);
}

// ---------------- edge-conv BN+lrelu+max_k ----------------
__global__ void k_edge_apply(const float* __restrict__ gamma, const float* __restrict__ beta, int c0out) {
    int n = blockIdx.x * 256 + threadIdx.x, o = blockIdx.y, b = blockIdx.z;
    float m = d_mean[o], r = d_rstd[o], g = gamma[o], be = beta[o];
    const float* Ab = d_AC + ((long)b * 128 + o) * Npt;
    float cc = d_AC[((long)b * 128 + 64 + o) * Npt + n];
    const int* ip = d_idx + (b * Npt + n) * KNN;
    float best = -FLT_MAX;
    #pragma unroll 4
    for (int k = 0; k < KNN; k++) {
        float v = Ab[ip[k]] + cc;
        v = lrelu((v - m) * r * g + be);
        best = fmaxf(best, v);
    }
    d_xcat[((long)b * 192 + c0out + o) * Npt + n] = best;
}

// ---------------- fused stats + BN + lrelu + max over n -> gmax (fp32 Kahan) ----------------
__global__ void k_stats_gmax(const float* __restrict__ buf,
                             const float* __restrict__ gamma, const float* __restrict__ beta) {
    int o = blockIdx.x;  // 512
    float s = 0.f, sc = 0.f, s2 = 0.f, s2c = 0.f;
    for (int i = threadIdx.x; i < Bsz * Npt; i += 256) {
        int b = i >> 12, n = i & (Npt - 1);
        float v = buf[((long)b * 512 + o) * Npt + n];
        kadd(s, sc, v);
        kadd(s2, s2c, v * v);
    }
    __shared__ float sh[256], sh2[256];
    __shared__ float smv, srv;
    sh[threadIdx.x] = s; sh2[threadIdx.x] = s2; __syncthreads();
    for (int st = 128; st > 0; st >>= 1) {
        if (threadIdx.x < st) { sh[threadIdx.x] += sh[threadIdx.x + st]; sh2[threadIdx.x] += sh2[threadIdx.x + st]; }
        __syncthreads();
    }
    if (threadIdx.x == 0) {
        float cnt = (float)(Bsz * Npt);
        float m = sh[0] / cnt;
        float var = sh2[0] / cnt - m * m;
        smv = m;
        srv = rsqrtf(fmaxf(var, 0.f) + EPSBN);
    }
    __syncthreads();
    float m = smv, r = srv, g = gamma[o], be = beta[o];
    __shared__ float shm[256];
    for (int b = 0; b < Bsz; b++) {
        float best = -FLT_MAX;
        for (int n = threadIdx.x; n < Npt; n += 256) {
            float v = buf[((long)b * 512 + o) * Npt + n];
            best = fmaxf(best, lrelu((v - m) * r * g + be));
        }
        shm[threadIdx.x] = best; __syncthreads();
        for (int st = 128; st > 0; st >>= 1) {
            if (threadIdx.x < st) shm[threadIdx.x] = fmaxf(shm[threadIdx.x], shm[threadIdx.x + st]);
            __syncthreads();
        }
        if (threadIdx.x == 0) d_gmax[b * 512 + o] = shm[0];
        __syncthreads();
    }
}

// ---------------- fold W5[:,192:] @ broadcast(gmax) into a per-(b,o) bias ----------------
__global__ void k_bias5(const float* __restrict__ W5) {
    int t = blockIdx.x * 128 + threadIdx.x;
    int b = t >> 9, o = t & 511;
    float s = 0.f;
    #pragma unroll 8
    for (int c = 0; c < 512; c++)
        s += W5[(long)o * 704 + 192 + c] * d_gmax[b * 512 + c];
    d_bias5[b * 512 + o] = s;
}

// ---------------- final conv 128 -> 2 + bias ----------------
__global__ void k_final(const float* __restrict__ W8, const float* __restrict__ b8,
                        float* __restrict__ out) {
    int n = blockIdx.x * 256 + threadIdx.x, b = blockIdx.y;
    float s0 = b8[0], s1 = b8[1];
    #pragma unroll 8
    for (int c = 0; c < 128; c++) {
        float h = d_y7[((long)b * 128 + c) * Npt + n];
        s0 += W8[c] * h;
        s1 += W8[128 + c] * h;
    }
    out[(b * 2 + 0) * Npt + n] = s0;
    out[(b * 2 + 1) * Npt + n] = s1;
}

// ---------------- host ----------------
extern "C" void kernel_launch(void* const* d_in, const int* in_sizes, int n_in,
                              void* d_out, int out_size) {
    (void)in_sizes; (void)n_in; (void)out_size;
    const float* x   = (const float*)d_in[0];
    const float* W1  = (const float*)d_in[1];
    const float* W2  = (const float*)d_in[2];
    const float* W3  = (const float*)d_in[3];
    const float* W4  = (const float*)d_in[4];
    const float* W5  = (const float*)d_in[5];
    const float* W6  = (const float*)d_in[6];
    const float* W7  = (const float*)d_in[7];
    const float* W8  = (const float*)d_in[8];
    const float* b8  = (const float*)d_in[9];
    const float* g1 = (const float*)d_in[10], *bb1 = (const float*)d_in[11];
    const float* g2 = (const float*)d_in[12], *bb2 = (const float*)d_in[13];
    const float* g3 = (const float*)d_in[14], *bb3 = (const float*)d_in[15];
    const float* g4 = (const float*)d_in[16], *bb4 = (const float*)d_in[17];
    const float* g5 = (const float*)d_in[18], *bb5 = (const float*)d_in[19];
    const float* g6 = (const float*)d_in[20], *bb6 = (const float*)d_in[21];
    const float* g7 = (const float*)d_in[22], *bb7 = (const float*)d_in[23];

    void *pv;
    cudaGetSymbolAddress(&pv, d_xcat);  float* p_xcat = (float*)pv;
    cudaGetSymbolAddress(&pv, d_AC);    float* p_AC   = (float*)pv;
    cudaGetSymbolAddress(&pv, d_y4);    float* p_y4   = (float*)pv;
    cudaGetSymbolAddress(&pv, d_y5);    float* p_y5   = (float*)pv;
    cudaGetSymbolAddress(&pv, d_y6);    float* p_y6   = (float*)pv;
    cudaGetSymbolAddress(&pv, d_y7);    float* p_y7   = (float*)pv;
    cudaGetSymbolAddress(&pv, d_bias5); float* p_b5   = (float*)pv;
    cudaGetSymbolAddress(&pv, d_Wc2);   float* p_Wc2  = (float*)pv;
    cudaGetSymbolAddress(&pv, d_Wc3);   float* p_Wc3  = (float*)pv;

    // conv1 + BN + lrelu -> x1 (xcat[0:64))
    k_conv1<<<dim3(16, 64, 4), 256>>>(x, W1);
    k_statsapply<<<64, 256>>>(p_xcat, 192, 0, g1, bb1);

    // kNN round 1 on x1: dist + group max -> top-21 groups -> exact top-20
    k_dist128<<<dim3(32, 32, 4), 256>>>(0);
    k_groupsel<<<2048, 256>>>();
    k_gather_topk<<<2048, 256>>>();

    // edge-conv 2 -> x2 (xcat[64:128))
    k_prepw<<<64, 64>>>(W2, p_Wc2);
    k_gemm128<<<dim3(32, 1, 4), 256>>>(p_AC, p_xcat, p_Wc2, nullptr, 64, 64, 192, 0, 128, 0);
    k_edge_stats_part<<<dim3(64, 8), 256>>>();
    k_edge_stats_fin<<<1, 64>>>();
    k_edge_apply<<<dim3(16, 64, 4), 256>>>(g2, bb2, 64);

    // kNN round 2 on x2
    k_dist128<<<dim3(32, 32, 4), 256>>>(64);
    k_groupsel<<<2048, 256>>>();
    k_gather_topk<<<2048, 256>>>();

    // edge-conv 3 -> x3 (xcat[128:192))
    k_prepw<<<64, 64>>>(W3, p_Wc3);
    k_gemm128<<<dim3(32, 1, 4), 256>>>(p_AC, p_xcat, p_Wc3, nullptr, 64, 64, 192, 64, 128, 0);
    k_edge_stats_part<<<dim3(64, 8), 256>>>();
    k_edge_stats_fin<<<1, 64>>>();
    k_edge_apply<<<dim3(16, 64, 4), 256>>>(g3, bb3, 128);

    // global branch: y4 = W4 @ x3; fused stats+BN+lrelu+max -> gmax; fold into bias5
    k_gemm128<<<dim3(32, 4, 4), 256>>>(p_y4, p_xcat, W4, nullptr, 64, 64, 192, 128, 512, 0);
    k_stats_gmax<<<512, 256>>>(p_y4, g4, bb4);
    k_bias5<<<16, 128>>>(W5);

    // W5 on [x1;x2;x3] (C=192) + bias5; BN; lrelu
    k_gemm128<<<dim3(32, 4, 4), 256>>>(p_y5, p_xcat, W5, p_b5, 192, 704, 192, 0, 512, 0);
    k_statsapply<<<512, 256>>>(p_y5, 512, 0, g5, bb5);

    // W6
    k_gemm128<<<dim3(32, 2, 4), 256>>>(p_y6, p_y5, W6, nullptr, 512, 512, 512, 0, 256, 0);
    k_statsapply<<<256, 256>>>(p_y6, 256, 0, g6, bb6);

    // W7
    k_gemm128<<<dim3(32, 1, 4), 256>>>(p_y7, p_y6, W7, nullptr, 256, 256, 256, 0, 128, 0);
    k_statsapply<<<128, 256>>>(p_y7, 128, 0, g7, bb7);

    // final 128 -> 2
    k_final<<<dim3(16, 4), 256>>>(W8, b8, (float*)d_out);
}

// round 9
// speedup vs baseline: 2.4737x; 1.1283x over previous
#include <cuda_runtime.h>
#include <math.h>
#include <float.h>

#define Bsz 4
#define Npt 4096
#define KNN 20
#define EPSBN 1e-5f
#define NROWS (Bsz * Npt)
#define NGRP 512          // 8-col groups per row
#define KG 21             // groups kept (top-20 + 1 tie guard)

// ---------------- scratch (device globals; no allocations) ----------------
__device__ float d_dist[(size_t)Bsz * Npt * Npt];   // 268 MB distance matrix
__device__ float d_g8[(size_t)NROWS * NGRP];        // per-row 8-col group maxes
__device__ float d_xcat[Bsz * 192 * Npt];           // x1|x2|x3 concatenated
__device__ float d_AC[Bsz * 128 * Npt];             // A (0:64) | Cc (64:128)
__device__ float d_y5[Bsz * 512 * Npt];
__device__ float d_y4[Bsz * 512 * Npt];
__device__ float d_y6[Bsz * 256 * Npt];
__device__ float d_y7[Bsz * 128 * Npt];
__device__ int   d_idx[Bsz * Npt * KNN];
__device__ float d_gmax[Bsz * 512];
__device__ float d_bias5[Bsz * 512];
__device__ float d_Wc2[128 * 64], d_Wc3[128 * 64];
__device__ float d_mean[64];
__device__ float d_rstd[64];
__device__ float d_espart[64 * 8 * 2];   // edge-stats partials (s, s2)

__device__ __forceinline__ float lrelu(float v) { return v >= 0.f ? v : 0.2f * v; }

// Kahan-compensated fp32 accumulator
__device__ __forceinline__ void kadd(float& s, float& c, float v) {
    float y = v - c;
    float t = s + y;
    c = (t - s) - y;
    s = t;
}

// ---------------- conv1: 3 -> 64 ----------------
__global__ void k_conv1(const float* __restrict__ x, const float* __restrict__ W1) {
    int n = blockIdx.x * 256 + threadIdx.x;
    int o = blockIdx.y, b = blockIdx.z;
    float v = W1[o * 3 + 0] * x[(b * 3 + 0) * Npt + n]
            + W1[o * 3 + 1] * x[(b * 3 + 1) * Npt + n]
            + W1[o * 3 + 2] * x[(b * 3 + 2) * Npt + n];
    d_xcat[((long)b * 192 + o) * Npt + n] = v;
}

// ---------------- fused BN stats + apply + lrelu (in place, fp32 Kahan) ----------------
__global__ void k_statsapply(float* __restrict__ buf, int CT, int c0,
                             const float* __restrict__ gamma, const float* __restrict__ beta) {
    int o = blockIdx.x;
    float s = 0.f, sc = 0.f, s2 = 0.f, s2c = 0.f;
    for (int i = threadIdx.x; i < Bsz * Npt; i += 256) {
        int b = i >> 12, n = i & (Npt - 1);
        float v = buf[((long)b * CT + c0 + o) * Npt + n];
        kadd(s, sc, v);
        kadd(s2, s2c, v * v);
    }
    __shared__ float sh[256], sh2[256];
    __shared__ float smv, srv;
    sh[threadIdx.x] = s; sh2[threadIdx.x] = s2; __syncthreads();
    for (int st = 128; st > 0; st >>= 1) {
        if (threadIdx.x < st) { sh[threadIdx.x] += sh[threadIdx.x + st]; sh2[threadIdx.x] += sh2[threadIdx.x + st]; }
        __syncthreads();
    }
    if (threadIdx.x == 0) {
        float cnt = (float)(Bsz * Npt);
        float m = sh[0] / cnt;
        float var = sh2[0] / cnt - m * m;
        smv = m;
        srv = rsqrtf(fmaxf(var, 0.f) + EPSBN);
    }
    __syncthreads();
    float m = smv, r = srv, g = gamma[o], be = beta[o];
    for (int i = threadIdx.x; i < Bsz * Npt; i += 256) {
        int b = i >> 12, n = i & (Npt - 1);
        long off = ((long)b * CT + c0 + o) * Npt + n;
        buf[off] = lrelu((buf[off] - m) * r * g + be);
    }
}

// ======== symmetric 128x128 tile distance GEMM (qs <= ns only) ========
// normal block: rows q, value 2*dot - sq[n]; transposed block: rows n, value 2*dot - sq[q].
// Both sides' 8-col group maxes computed from registers. Row-constant offsets dropped (order-safe).
__global__ void __launch_bounds__(256, 1) k_dist_sym(int c0) {
    int ns = blockIdx.x, qs = blockIdx.y, b = blockIdx.z;
    if (ns < qs) return;
    __shared__ float Qs[16][132];
    __shared__ float Ms[16][132];
    __shared__ float sqQ[128], sqM[128];
    int q0 = qs * 128, n0 = ns * 128;
    int tid = threadIdx.x, tx = tid & 15, ty = tid >> 4;
    float acc[2][2][4][4] = {};
    float myssq = 0.f;
    const float* xb = d_xcat + ((long)b * 192 + c0) * Npt;
    #pragma unroll 1
    for (int ck = 0; ck < 64; ck += 16) {
        #pragma unroll
        for (int r = 0; r < 8; r++) {
            int idx = r * 256 + tid;
            int cc = idx >> 7, e = idx & 127;
            long rowoff = (long)(ck + cc) * Npt;
            Qs[cc][e] = xb[rowoff + q0 + e];
            Ms[cc][e] = xb[rowoff + n0 + e];
        }
        __syncthreads();
        if (tid < 128) {
            #pragma unroll
            for (int cc = 0; cc < 16; cc++) {
                float v = Ms[cc][tid];
                myssq += v * v;
            }
        } else {
            int t2 = tid - 128;
            #pragma unroll
            for (int cc = 0; cc < 16; cc++) {
                float v = Qs[cc][t2];
                myssq += v * v;
            }
        }
        #pragma unroll
        for (int k = 0; k < 16; k++) {
            float4 a0 = *(const float4*)&Qs[k][ty * 4];
            float4 a1 = *(const float4*)&Qs[k][64 + ty * 4];
            float4 b0 = *(const float4*)&Ms[k][tx * 4];
            float4 b1 = *(const float4*)&Ms[k][64 + tx * 4];
            float aa[2][4] = {{a0.x, a0.y, a0.z, a0.w}, {a1.x, a1.y, a1.z, a1.w}};
            float bb[2][4] = {{b0.x, b0.y, b0.z, b0.w}, {b1.x, b1.y, b1.z, b1.w}};
            #pragma unroll
            for (int ii = 0; ii < 2; ii++)
                #pragma unroll
                for (int i = 0; i < 4; i++)
                    #pragma unroll
                    for (int jj = 0; jj < 2; jj++)
                        #pragma unroll
                        for (int j = 0; j < 4; j++)
                            acc[ii][jj][i][j] += aa[ii][i] * bb[jj][j];
        }
        __syncthreads();
    }
    if (tid < 128) sqM[tid] = myssq; else sqQ[tid - 128] = myssq;
    __syncthreads();
    long bN = (long)b * Npt;
    // -------- normal block: rows q, cols n --------
    {
        float sn0[4], sn1[4];
        #pragma unroll
        for (int j = 0; j < 4; j++) {
            sn0[j] = sqM[tx * 4 + j];
            sn1[j] = sqM[64 + tx * 4 + j];
        }
        #pragma unroll
        for (int ii = 0; ii < 2; ii++) {
            #pragma unroll
            for (int i = 0; i < 4; i++) {
                int q = q0 + ii * 64 + ty * 4 + i;
                float* row = d_dist + (bN + q) * Npt + n0;
                float4 v0, v1;
                v0.x = 2.f * acc[ii][0][i][0] - sn0[0];
                v0.y = 2.f * acc[ii][0][i][1] - sn0[1];
                v0.z = 2.f * acc[ii][0][i][2] - sn0[2];
                v0.w = 2.f * acc[ii][0][i][3] - sn0[3];
                v1.x = 2.f * acc[ii][1][i][0] - sn1[0];
                v1.y = 2.f * acc[ii][1][i][1] - sn1[1];
                v1.z = 2.f * acc[ii][1][i][2] - sn1[2];
                v1.w = 2.f * acc[ii][1][i][3] - sn1[3];
                *(float4*)&row[tx * 4] = v0;
                *(float4*)&row[64 + tx * 4] = v1;
                float m01 = fmaxf(fmaxf(v0.x, v0.y), fmaxf(v0.z, v0.w));
                float m23 = fmaxf(fmaxf(v1.x, v1.y), fmaxf(v1.z, v1.w));
                d_g8[(bN + q) * NGRP + ns * 16 + tx] = fmaxf(m01, m23);
            }
        }
    }
    // -------- transposed block: rows n, cols q (skip on diagonal) --------
    if (ns != qs) {
        float sq0[4], sq1[4];
        #pragma unroll
        for (int i = 0; i < 4; i++) {
            sq0[i] = sqQ[ty * 4 + i];
            sq1[i] = sqQ[64 + ty * 4 + i];
        }
        #pragma unroll
        for (int jj = 0; jj < 2; jj++) {
            #pragma unroll
            for (int j = 0; j < 4; j++) {
                int n = n0 + jj * 64 + tx * 4 + j;
                float* row = d_dist + (bN + n) * Npt;
                float4 w0, w1;
                w0.x = 2.f * acc[0][jj][0][j] - sq0[0];
                w0.y = 2.f * acc[0][jj][1][j] - sq0[1];
                w0.z = 2.f * acc[0][jj][2][j] - sq0[2];
                w0.w = 2.f * acc[0][jj][3][j] - sq0[3];
                w1.x = 2.f * acc[1][jj][0][j] - sq1[0];
                w1.y = 2.f * acc[1][jj][1][j] - sq1[1];
                w1.z = 2.f * acc[1][jj][2][j] - sq1[2];
                w1.w = 2.f * acc[1][jj][3][j] - sq1[3];
                *(float4*)&row[q0 + ty * 4] = w0;
                *(float4*)&row[q0 + 64 + ty * 4] = w1;
                float m01 = fmaxf(fmaxf(w0.x, w0.y), fmaxf(w0.z, w0.w));
                float m23 = fmaxf(fmaxf(w1.x, w1.y), fmaxf(w1.z, w1.w));
                d_g8[(bN + n) * NGRP + qs * 16 + ty] = fmaxf(m01, m23);
            }
        }
    }
}

// ---------------- fused warp-per-row: top-21 groups then exact top-20 ----------------
__global__ void k_knn_select() {
    int warp = threadIdx.x >> 5, lane = threadIdx.x & 31;
    int row = blockIdx.x * 8 + warp;
    const float* g = d_g8 + (long)row * NGRP;
    float v[16];
    #pragma unroll
    for (int j = 0; j < 16; j++) v[j] = g[lane + 32 * j];
    float lmax = v[0]; int lj = 0;
    #pragma unroll
    for (int j = 1; j < 16; j++) if (v[j] > lmax) { lmax = v[j]; lj = j; }
    int mygroup = 0;   // lane t holds the t-th selected group (t < KG)
    #pragma unroll 1
    for (int t = 0; t < KG; t++) {
        float bv = lmax; int bidx = lane + 32 * lj;
        #pragma unroll
        for (int off = 16; off > 0; off >>= 1) {
            float ov = __shfl_xor_sync(0xffffffffu, bv, off);
            int oi = __shfl_xor_sync(0xffffffffu, bidx, off);
            if (ov > bv || (ov == bv && oi < bidx)) { bv = ov; bidx = oi; }
        }
        if (lane == t) mygroup = bidx;
        if ((bidx & 31) == lane) {
            int s = bidx >> 5;
            #pragma unroll
            for (int j = 0; j < 16; j++) if (j == s) v[j] = -FLT_MAX;
            lmax = v[0]; lj = 0;
            #pragma unroll
            for (int j = 1; j < 16; j++) if (v[j] > lmax) { lmax = v[j]; lj = j; }
        }
    }
    // gather phase: lanes 0..20 each own one group (8 candidates)
    const float* drow = d_dist + (long)row * Npt;
    float c[8];
    int base = 0;
    if (lane < KG) {
        base = (mygroup >> 4) * 128 + (mygroup & 15) * 4;
        float4 a = *(const float4*)&drow[base];
        float4 bb = *(const float4*)&drow[base + 64];
        c[0] = a.x;  c[1] = a.y;  c[2] = a.z;  c[3] = a.w;
        c[4] = bb.x; c[5] = bb.y; c[6] = bb.z; c[7] = bb.w;
    } else {
        #pragma unroll
        for (int j = 0; j < 8; j++) c[j] = -FLT_MAX;
    }
    float cmax = c[0]; int cj = 0;
    #pragma unroll
    for (int j = 1; j < 8; j++) if (c[j] > cmax) { cmax = c[j]; cj = j; }
    #pragma unroll 1
    for (int t = 0; t < KNN; t++) {
        int lidx = base + (cj < 4 ? cj : 60 + cj);
        float bv = cmax; int bidx = lidx;
        #pragma unroll
        for (int off = 16; off > 0; off >>= 1) {
            float ov = __shfl_xor_sync(0xffffffffu, bv, off);
            int oi = __shfl_xor_sync(0xffffffffu, bidx, off);
            if (ov > bv || (ov == bv && oi < bidx)) { bv = ov; bidx = oi; }
        }
        if (lane == 0) d_idx[row * KNN + t] = bidx;
        if (bv == cmax && bidx == lidx) {
            #pragma unroll
            for (int j = 0; j < 8; j++) if (j == cj) c[j] = -FLT_MAX;
            cmax = c[0]; cj = 0;
            #pragma unroll
            for (int j = 1; j < 8; j++) if (c[j] > cmax) { cmax = c[j]; cj = j; }
        }
    }
}

// ---------------- combined weight prep ----------------
__global__ void k_prepw(const float* __restrict__ W, float* __restrict__ Wc) {
    int o = blockIdx.x, c = threadIdx.x;
    float a = W[o * 128 + c], bb = W[o * 128 + 64 + c];
    Wc[o * 64 + c] = a;
    Wc[(64 + o) * 64 + c] = bb - a;
}

// ======== 128x128 tile feature GEMM ========
__global__ void __launch_bounds__(256, 1) k_gemm128(
        float* __restrict__ out, const float* __restrict__ in,
        const float* __restrict__ W, const float* __restrict__ biasBO,
        int C, int ldw, int CTin, int c0in, int CTout, int c0out) {
    __shared__ float Ws[16][132];
    __shared__ float Xs[16][128];
    int b = blockIdx.z, o0 = blockIdx.y * 128, n0 = blockIdx.x * 128;
    int tid = threadIdx.x, tx = tid & 15, ty = tid >> 4;
    float acc[2][2][4][4] = {};
    const float* inB = in + ((long)b * CTin + c0in) * Npt + n0;
    #pragma unroll 1
    for (int ck = 0; ck < C; ck += 16) {
        #pragma unroll
        for (int r = 0; r < 8; r++) {
            int idx = r * 256 + tid;
            int oo = idx >> 4, cc = idx & 15;
            Ws[cc][oo] = W[(long)(o0 + oo) * ldw + ck + cc];
        }
        #pragma unroll
        for (int r = 0; r < 8; r++) {
            int idx = r * 256 + tid;
            int cc = idx >> 7, e = idx & 127;
            Xs[cc][e] = inB[(long)(ck + cc) * Npt + e];
        }
        __syncthreads();
        #pragma unroll
        for (int k = 0; k < 16; k++) {
            float4 a0 = *(const float4*)&Ws[k][ty * 4];
            float4 a1 = *(const float4*)&Ws[k][64 + ty * 4];
            float4 b0 = *(const float4*)&Xs[k][tx * 4];
            float4 b1 = *(const float4*)&Xs[k][64 + tx * 4];
            float aa[2][4] = {{a0.x, a0.y, a0.z, a0.w}, {a1.x, a1.y, a1.z, a1.w}};
            float bb[2][4] = {{b0.x, b0.y, b0.z, b0.w}, {b1.x, b1.y, b1.z, b1.w}};
            #pragma unroll
            for (int ii = 0; ii < 2; ii++)
                #pragma unroll
                for (int i = 0; i < 4; i++)
                    #pragma unroll
                    for (int jj = 0; jj < 2; jj++)
                        #pragma unroll
                        for (int j = 0; j < 4; j++)
                            acc[ii][jj][i][j] += aa[ii][i] * bb[jj][j];
        }
        __syncthreads();
    }
    #pragma unroll
    for (int ii = 0; ii < 2; ii++) {
        #pragma unroll
        for (int i = 0; i < 4; i++) {
            int o = o0 + ii * 64 + ty * 4 + i;
            float bias = biasBO ? biasBO[b * 512 + o] : 0.f;
            float* row = out + ((long)b * CTout + c0out + o) * Npt + n0;
            float4 v0, v1;
            v0.x = acc[ii][0][i][0] + bias; v0.y = acc[ii][0][i][1] + bias;
            v0.z = acc[ii][0][i][2] + bias; v0.w = acc[ii][0][i][3] + bias;
            v1.x = acc[ii][1][i][0] + bias; v1.y = acc[ii][1][i][1] + bias;
            v1.z = acc[ii][1][i][2] + bias; v1.w = acc[ii][1][i][3] + bias;
            *(float4*)&row[tx * 4] = v0;
            *(float4*)&row[64 + tx * 4] = v1;
        }
    }
}

// ---------------- edge-conv BN stats: stage 1 (64 channels x 8 slices) ----------------
__global__ void k_edge_stats_part() {
    int o = blockIdx.x, slice = blockIdx.y;
    int tid = threadIdx.x;
    float s = 0.f, sc = 0.f, s2 = 0.f, s2c = 0.f;
    #pragma unroll 1
    for (int b = 0; b < Bsz; b++) {
        const float* Ab = d_AC + ((long)b * 128 + o) * Npt;
        const float* Cb = d_AC + ((long)b * 128 + 64 + o) * Npt;
        #pragma unroll 1
        for (int n = slice * 512 + tid; n < (slice + 1) * 512; n += 256) {
            float cc = Cb[n];
            const int* ip = d_idx + ((long)(b * Npt + n)) * KNN;
            #pragma unroll 4
            for (int k = 0; k < KNN; k++) {
                float v = Ab[ip[k]] + cc;
                kadd(s, sc, v);
                kadd(s2, s2c, v * v);
            }
        }
    }
    __shared__ float sh[256], sh2[256];
    sh[tid] = s; sh2[tid] = s2; __syncthreads();
    for (int st = 128; st > 0; st >>= 1) {
        if (tid < st) { sh[tid] += sh[tid + st]; sh2[tid] += sh2[tid + st]; }
        __syncthreads();
    }
    if (tid == 0) {
        d_espart[(o * 8 + slice) * 2 + 0] = sh[0];
        d_espart[(o * 8 + slice) * 2 + 1] = sh2[0];
    }
}

// ---------------- edge-conv BN stats: finalize ----------------
__global__ void k_edge_stats_fin() {
    int o = threadIdx.x;  // 64
    float s = 0.f, s2 = 0.f;
    #pragma unroll
    for (int p = 0; p < 8; p++) {
        s += d_espart[(o * 8 + p) * 2 + 0];
        s2 += d_espart[(o * 8 + p) * 2 + 1];
    }
    float cnt = (float)(Bsz * Npt * KNN);
    float m = s / cnt;
    float var = s2 / cnt - m * m;
    d_mean[o] = m;
    d_rstd[o] = rsqrtf(fmaxf(var, 0.f) + EPSBN);
}

// ---------------- edge-conv BN+lrelu+max_k ----------------
__global__ void k_edge_apply(const float* __restrict__ gamma, const float* __restrict__ beta, int c0out) {
    int n = blockIdx.x * 256 + threadIdx.x, o = blockIdx.y, b = blockIdx.z;
    float m = d_mean[o], r = d_rstd[o], g = gamma[o], be = beta[o];
    const float* Ab = d_AC + ((long)b * 128 + o) * Npt;
    float cc = d_AC[((long)b * 128 + 64 + o) * Npt + n];
    const int* ip = d_idx + (b * Npt + n) * KNN;
    float best = -FLT_MAX;
    #pragma unroll 4
    for (int k = 0; k < KNN; k++) {
        float v = Ab[ip[k]] + cc;
        v = lrelu((v - m) * r * g + be);
        best = fmaxf(best, v);
    }
    d_xcat[((long)b * 192 + c0out + o) * Npt + n] = best;
}

// ---------------- fused stats + BN + lrelu + max over n -> gmax (fp32 Kahan) ----------------
__global__ void k_stats_gmax(const float* __restrict__ buf,
                             const float* __restrict__ gamma, const float* __restrict__ beta) {
    int o = blockIdx.x;  // 512
    float s = 0.f, sc = 0.f, s2 = 0.f, s2c = 0.f;
    for (int i = threadIdx.x; i < Bsz * Npt; i += 256) {
        int b = i >> 12, n = i & (Npt - 1);
        float v = buf[((long)b * 512 + o) * Npt + n];
        kadd(s, sc, v);
        kadd(s2, s2c, v * v);
    }
    __shared__ float sh[256], sh2[256];
    __shared__ float smv, srv;
    sh[threadIdx.x] = s; sh2[threadIdx.x] = s2; __syncthreads();
    for (int st = 128; st > 0; st >>= 1) {
        if (threadIdx.x < st) { sh[threadIdx.x] += sh[threadIdx.x + st]; sh2[threadIdx.x] += sh2[threadIdx.x + st]; }
        __syncthreads();
    }
    if (threadIdx.x == 0) {
        float cnt = (float)(Bsz * Npt);
        float m = sh[0] / cnt;
        float var = sh2[0] / cnt - m * m;
        smv = m;
        srv = rsqrtf(fmaxf(var, 0.f) + EPSBN);
    }
    __syncthreads();
    float m = smv, r = srv, g = gamma[o], be = beta[o];
    __shared__ float shm[256];
    for (int b = 0; b < Bsz; b++) {
        float best = -FLT_MAX;
        for (int n = threadIdx.x; n < Npt; n += 256) {
            float v = buf[((long)b * 512 + o) * Npt + n];
            best = fmaxf(best, lrelu((v - m) * r * g + be));
        }
        shm[threadIdx.x] = best; __syncthreads();
        for (int st = 128; st > 0; st >>= 1) {
            if (threadIdx.x < st) shm[threadIdx.x] = fmaxf(shm[threadIdx.x], shm[threadIdx.x + st]);
            __syncthreads();
        }
        if (threadIdx.x == 0) d_gmax[b * 512 + o] = shm[0];
        __syncthreads();
    }
}

// ---------------- fold W5[:,192:] @ broadcast(gmax) into a per-(b,o) bias ----------------
__global__ void k_bias5(const float* __restrict__ W5) {
    int t = blockIdx.x * 128 + threadIdx.x;
    int b = t >> 9, o = t & 511;
    float s = 0.f;
    #pragma unroll 8
    for (int c = 0; c < 512; c++)
        s += W5[(long)o * 704 + 192 + c] * d_gmax[b * 512 + c];
    d_bias5[b * 512 + o] = s;
}

// ---------------- final conv 128 -> 2 + bias ----------------
__global__ void k_final(const float* __restrict__ W8, const float* __restrict__ b8,
                        float* __restrict__ out) {
    int n = blockIdx.x * 256 + threadIdx.x, b = blockIdx.y;
    float s0 = b8[0], s1 = b8[1];
    #pragma unroll 8
    for (int c = 0; c < 128; c++) {
        float h = d_y7[((long)b * 128 + c) * Npt + n];
        s0 += W8[c] * h;
        s1 += W8[128 + c] * h;
    }
    out[(b * 2 + 0) * Npt + n] = s0;
    out[(b * 2 + 1) * Npt + n] = s1;
}

// ---------------- host ----------------
extern "C" void kernel_launch(void* const* d_in, const int* in_sizes, int n_in,
                              void* d_out, int out_size) {
    (void)in_sizes; (void)n_in; (void)out_size;
    const float* x   = (const float*)d_in[0];
    const float* W1  = (const float*)d_in[1];
    const float* W2  = (const float*)d_in[2];
    const float* W3  = (const float*)d_in[3];
    const float* W4  = (const float*)d_in[4];
    const float* W5  = (const float*)d_in[5];
    const float* W6  = (const float*)d_in[6];
    const float* W7  = (const float*)d_in[7];
    const float* W8  = (const float*)d_in[8];
    const float* b8  = (const float*)d_in[9];
    const float* g1 = (const float*)d_in[10], *bb1 = (const float*)d_in[11];
    const float* g2 = (const float*)d_in[12], *bb2 = (const float*)d_in[13];
    const float* g3 = (const float*)d_in[14], *bb3 = (const float*)d_in[15];
    const float* g4 = (const float*)d_in[16], *bb4 = (const float*)d_in[17];
    const float* g5 = (const float*)d_in[18], *bb5 = (const float*)d_in[19];
    const float* g6 = (const float*)d_in[20], *bb6 = (const float*)d_in[21];
    const float* g7 = (const float*)d_in[22], *bb7 = (const float*)d_in[23];

    void *pv;
    cudaGetSymbolAddress(&pv, d_xcat);  float* p_xcat = (float*)pv;
    cudaGetSymbolAddress(&pv, d_AC);    float* p_AC   = (float*)pv;
    cudaGetSymbolAddress(&pv, d_y4);    float* p_y4   = (float*)pv;
    cudaGetSymbolAddress(&pv, d_y5);    float* p_y5   = (float*)pv;
    cudaGetSymbolAddress(&pv, d_y6);    float* p_y6   = (float*)pv;
    cudaGetSymbolAddress(&pv, d_y7);    float* p_y7   = (float*)pv;
    cudaGetSymbolAddress(&pv, d_bias5); float* p_b5   = (float*)pv;
    cudaGetSymbolAddress(&pv, d_Wc2);   float* p_Wc2  = (float*)pv;
    cudaGetSymbolAddress(&pv, d_Wc3);   float* p_Wc3  = (float*)pv;

    // conv1 + BN + lrelu -> x1 (xcat[0:64))
    k_conv1<<<dim3(16, 64, 4), 256>>>(x, W1);
    k_statsapply<<<64, 256>>>(p_xcat, 192, 0, g1, bb1);

    // kNN round 1 on x1: symmetric dist + group max -> fused select
    k_dist_sym<<<dim3(32, 32, 4), 256>>>(0);
    k_knn_select<<<2048, 256>>>();

    // edge-conv 2 -> x2 (xcat[64:128))
    k_prepw<<<64, 64>>>(W2, p_Wc2);
    k_gemm128<<<dim3(32, 1, 4), 256>>>(p_AC, p_xcat, p_Wc2, nullptr, 64, 64, 192, 0, 128, 0);
    k_edge_stats_part<<<dim3(64, 8), 256>>>();
    k_edge_stats_fin<<<1, 64>>>();
    k_edge_apply<<<dim3(16, 64, 4), 256>>>(g2, bb2, 64);

    // kNN round 2 on x2
    k_dist_sym<<<dim3(32, 32, 4), 256>>>(64);
    k_knn_select<<<2048, 256>>>();

    // edge-conv 3 -> x3 (xcat[128:192))
    k_prepw<<<64, 64>>>(W3, p_Wc3);
    k_gemm128<<<dim3(32, 1, 4), 256>>>(p_AC, p_xcat, p_Wc3, nullptr, 64, 64, 192, 64, 128, 0);
    k_edge_stats_part<<<dim3(64, 8), 256>>>();
    k_edge_stats_fin<<<1, 64>>>();
    k_edge_apply<<<dim3(16, 64, 4), 256>>>(g3, bb3, 128);

    // global branch: y4 = W4 @ x3; fused stats+BN+lrelu+max -> gmax; fold into bias5
    k_gemm128<<<dim3(32, 4, 4), 256>>>(p_y4, p_xcat, W4, nullptr, 64, 64, 192, 128, 512, 0);
    k_stats_gmax<<<512, 256>>>(p_y4, g4, bb4);
    k_bias5<<<16, 128>>>(W5);

    // W5 on [x1;x2;x3] (C=192) + bias5; BN; lrelu
    k_gemm128<<<dim3(32, 4, 4), 256>>>(p_y5, p_xcat, W5, p_b5, 192, 704, 192, 0, 512, 0);
    k_statsapply<<<512, 256>>>(p_y5, 512, 0, g5, bb5);

    // W6
    k_gemm128<<<dim3(32, 2, 4), 256>>>(p_y6, p_y5, W6, nullptr, 512, 512, 512, 0, 256, 0);
    k_statsapply<<<256, 256>>>(p_y6, 256, 0, g6, bb6);

    // W7
    k_gemm128<<<dim3(32, 1, 4), 256>>>(p_y7, p_y6, W7, nullptr, 256, 256, 256, 0, 128, 0);
    k_statsapply<<<128, 256>>>(p_y7, 128, 0, g7, bb7);

    // final 128 -> 2
    k_final<<<dim3(16, 4), 256>>>(W8, b8, (float*)d_out);
}

// round 10
// speedup vs baseline: 2.6090x; 1.0547x over previous
#include <cuda_runtime.h>
#include <math.h>
#include <float.h>

#define Bsz 4
#define Npt 4096
#define KNN 20
#define EPSBN 1e-5f
#define NROWS (Bsz * Npt)
#define NGRP 512          // 8-col groups per row
#define KG 21             // groups kept (top-20 + 1 tie guard)

// ---------------- scratch (device globals; no allocations) ----------------
__device__ float d_dist[(size_t)Bsz * Npt * Npt];   // 268 MB distance matrix
__device__ float d_g8[(size_t)NROWS * NGRP];        // per-row 8-col group maxes
__device__ float d_xcat[Bsz * 192 * Npt];           // x1|x2|x3 concatenated
__device__ float d_AC[Bsz * 128 * Npt];             // A (0:64) | Cc (64:128)
__device__ float d_y5[Bsz * 512 * Npt];
__device__ float d_y4[Bsz * 512 * Npt];
__device__ float d_y6[Bsz * 256 * Npt];
__device__ float d_y7[Bsz * 128 * Npt];
__device__ int   d_idx[Bsz * Npt * KNN];
__device__ float d_gmax[Bsz * 512];
__device__ float d_bias5[Bsz * 512];
__device__ float d_espart[64 * 8 * 2];   // edge-stats partials (s, s2)

__device__ __forceinline__ float lrelu(float v) { return v >= 0.f ? v : 0.2f * v; }

// order-preserving float->uint key (no NaNs in this data)
__device__ __forceinline__ unsigned fkey(float f) {
    unsigned u = __float_as_uint(f);
    return (u & 0x80000000u) ? ~u : (u | 0x80000000u);
}

// Kahan-compensated fp32 accumulator
__device__ __forceinline__ void kadd(float& s, float& c, float v) {
    float y = v - c;
    float t = s + y;
    c = (t - s) - y;
    s = t;
}

// ---------------- conv1: 3 -> 64 ----------------
__global__ void k_conv1(const float* __restrict__ x, const float* __restrict__ W1) {
    int n = blockIdx.x * 256 + threadIdx.x;
    int o = blockIdx.y, b = blockIdx.z;
    float v = W1[o * 3 + 0] * x[(b * 3 + 0) * Npt + n]
            + W1[o * 3 + 1] * x[(b * 3 + 1) * Npt + n]
            + W1[o * 3 + 2] * x[(b * 3 + 2) * Npt + n];
    d_xcat[((long)b * 192 + o) * Npt + n] = v;
}

// ---------------- fused BN stats + apply + lrelu (in place, fp32 Kahan) ----------------
__global__ void k_statsapply(float* __restrict__ buf, int CT, int c0,
                             const float* __restrict__ gamma, const float* __restrict__ beta) {
    int o = blockIdx.x;
    float s = 0.f, sc = 0.f, s2 = 0.f, s2c = 0.f;
    for (int i = threadIdx.x; i < Bsz * Npt; i += 256) {
        int b = i >> 12, n = i & (Npt - 1);
        float v = buf[((long)b * CT + c0 + o) * Npt + n];
        kadd(s, sc, v);
        kadd(s2, s2c, v * v);
    }
    __shared__ float sh[256], sh2[256];
    __shared__ float smv, srv;
    sh[threadIdx.x] = s; sh2[threadIdx.x] = s2; __syncthreads();
    for (int st = 128; st > 0; st >>= 1) {
        if (threadIdx.x < st) { sh[threadIdx.x] += sh[threadIdx.x + st]; sh2[threadIdx.x] += sh2[threadIdx.x + st]; }
        __syncthreads();
    }
    if (threadIdx.x == 0) {
        float cnt = (float)(Bsz * Npt);
        float m = sh[0] / cnt;
        float var = sh2[0] / cnt - m * m;
        smv = m;
        srv = rsqrtf(fmaxf(var, 0.f) + EPSBN);
    }
    __syncthreads();
    float m = smv, r = srv, g = gamma[o], be = beta[o];
    for (int i = threadIdx.x; i < Bsz * Npt; i += 256) {
        int b = i >> 12, n = i & (Npt - 1);
        long off = ((long)b * CT + c0 + o) * Npt + n;
        buf[off] = lrelu((buf[off] - m) * r * g + be);
    }
}

// ======== symmetric 128x128 tile distance GEMM (qs <= ns only) ========
__global__ void __launch_bounds__(256, 1) k_dist_sym(int c0) {
    int ns = blockIdx.x, qs = blockIdx.y, b = blockIdx.z;
    if (ns < qs) return;
    __shared__ float Qs[16][132];
    __shared__ float Ms[16][132];
    __shared__ float sqQ[128], sqM[128];
    int q0 = qs * 128, n0 = ns * 128;
    int tid = threadIdx.x, tx = tid & 15, ty = tid >> 4;
    float acc[2][2][4][4] = {};
    float myssq = 0.f;
    const float* xb = d_xcat + ((long)b * 192 + c0) * Npt;
    #pragma unroll 1
    for (int ck = 0; ck < 64; ck += 16) {
        #pragma unroll
        for (int r = 0; r < 8; r++) {
            int idx = r * 256 + tid;
            int cc = idx >> 7, e = idx & 127;
            long rowoff = (long)(ck + cc) * Npt;
            Qs[cc][e] = xb[rowoff + q0 + e];
            Ms[cc][e] = xb[rowoff + n0 + e];
        }
        __syncthreads();
        if (tid < 128) {
            #pragma unroll
            for (int cc = 0; cc < 16; cc++) {
                float v = Ms[cc][tid];
                myssq += v * v;
            }
        } else {
            int t2 = tid - 128;
            #pragma unroll
            for (int cc = 0; cc < 16; cc++) {
                float v = Qs[cc][t2];
                myssq += v * v;
            }
        }
        #pragma unroll
        for (int k = 0; k < 16; k++) {
            float4 a0 = *(const float4*)&Qs[k][ty * 4];
            float4 a1 = *(const float4*)&Qs[k][64 + ty * 4];
            float4 b0 = *(const float4*)&Ms[k][tx * 4];
            float4 b1 = *(const float4*)&Ms[k][64 + tx * 4];
            float aa[2][4] = {{a0.x, a0.y, a0.z, a0.w}, {a1.x, a1.y, a1.z, a1.w}};
            float bb[2][4] = {{b0.x, b0.y, b0.z, b0.w}, {b1.x, b1.y, b1.z, b1.w}};
            #pragma unroll
            for (int ii = 0; ii < 2; ii++)
                #pragma unroll
                for (int i = 0; i < 4; i++)
                    #pragma unroll
                    for (int jj = 0; jj < 2; jj++)
                        #pragma unroll
                        for (int j = 0; j < 4; j++)
                            acc[ii][jj][i][j] += aa[ii][i] * bb[jj][j];
        }
        __syncthreads();
    }
    if (tid < 128) sqM[tid] = myssq; else sqQ[tid - 128] = myssq;
    __syncthreads();
    long bN = (long)b * Npt;
    // -------- normal block: rows q, cols n --------
    {
        float sn0[4], sn1[4];
        #pragma unroll
        for (int j = 0; j < 4; j++) {
            sn0[j] = sqM[tx * 4 + j];
            sn1[j] = sqM[64 + tx * 4 + j];
        }
        #pragma unroll
        for (int ii = 0; ii < 2; ii++) {
            #pragma unroll
            for (int i = 0; i < 4; i++) {
                int q = q0 + ii * 64 + ty * 4 + i;
                float* row = d_dist + (bN + q) * Npt + n0;
                float4 v0, v1;
                v0.x = 2.f * acc[ii][0][i][0] - sn0[0];
                v0.y = 2.f * acc[ii][0][i][1] - sn0[1];
                v0.z = 2.f * acc[ii][0][i][2] - sn0[2];
                v0.w = 2.f * acc[ii][0][i][3] - sn0[3];
                v1.x = 2.f * acc[ii][1][i][0] - sn1[0];
                v1.y = 2.f * acc[ii][1][i][1] - sn1[1];
                v1.z = 2.f * acc[ii][1][i][2] - sn1[2];
                v1.w = 2.f * acc[ii][1][i][3] - sn1[3];
                *(float4*)&row[tx * 4] = v0;
                *(float4*)&row[64 + tx * 4] = v1;
                float m01 = fmaxf(fmaxf(v0.x, v0.y), fmaxf(v0.z, v0.w));
                float m23 = fmaxf(fmaxf(v1.x, v1.y), fmaxf(v1.z, v1.w));
                d_g8[(bN + q) * NGRP + ns * 16 + tx] = fmaxf(m01, m23);
            }
        }
    }
    // -------- transposed block: rows n, cols q (skip on diagonal) --------
    if (ns != qs) {
        float sq0[4], sq1[4];
        #pragma unroll
        for (int i = 0; i < 4; i++) {
            sq0[i] = sqQ[ty * 4 + i];
            sq1[i] = sqQ[64 + ty * 4 + i];
        }
        #pragma unroll
        for (int jj = 0; jj < 2; jj++) {
            #pragma unroll
            for (int j = 0; j < 4; j++) {
                int n = n0 + jj * 64 + tx * 4 + j;
                float* row = d_dist + (bN + n) * Npt;
                float4 w0, w1;
                w0.x = 2.f * acc[0][jj][0][j] - sq0[0];
                w0.y = 2.f * acc[0][jj][1][j] - sq0[1];
                w0.z = 2.f * acc[0][jj][2][j] - sq0[2];
                w0.w = 2.f * acc[0][jj][3][j] - sq0[3];
                w1.x = 2.f * acc[1][jj][0][j] - sq1[0];
                w1.y = 2.f * acc[1][jj][1][j] - sq1[1];
                w1.z = 2.f * acc[1][jj][2][j] - sq1[2];
                w1.w = 2.f * acc[1][jj][3][j] - sq1[3];
                *(float4*)&row[q0 + ty * 4] = w0;
                *(float4*)&row[q0 + 64 + ty * 4] = w1;
                float m01 = fmaxf(fmaxf(w0.x, w0.y), fmaxf(w0.z, w0.w));
                float m23 = fmaxf(fmaxf(w1.x, w1.y), fmaxf(w1.z, w1.w));
                d_g8[(bN + n) * NGRP + qs * 16 + ty] = fmaxf(m01, m23);
            }
        }
    }
}

// ---------------- fused warp-per-row kNN select (redux.sync argmax) ----------------
__global__ void k_knn_select() {
    int warp = threadIdx.x >> 5, lane = threadIdx.x & 31;
    int row = blockIdx.x * 8 + warp;
    const float* g = d_g8 + (long)row * NGRP;
    float v[16];
    #pragma unroll
    for (int j = 0; j < 16; j++) v[j] = g[lane + 32 * j];
    float lmax = v[0]; int lj = 0;
    #pragma unroll
    for (int j = 1; j < 16; j++) if (v[j] > lmax) { lmax = v[j]; lj = j; }
    unsigned lkey = fkey(lmax);
    int mygroup = 0;   // lane t holds the t-th selected group (t < KG)
    #pragma unroll 1
    for (int t = 0; t < KG; t++) {
        unsigned wkey = __reduce_max_sync(0xffffffffu, lkey);
        unsigned gid = (unsigned)(lane + 32 * lj);
        unsigned bidx = __reduce_min_sync(0xffffffffu, (lkey == wkey) ? gid : 0xffffffffu);
        if (lane == t) mygroup = (int)bidx;
        if (gid == bidx && lkey == wkey) {
            int s = (int)bidx >> 5;
            #pragma unroll
            for (int j = 0; j < 16; j++) if (j == s) v[j] = -FLT_MAX;
            lmax = v[0]; lj = 0;
            #pragma unroll
            for (int j = 1; j < 16; j++) if (v[j] > lmax) { lmax = v[j]; lj = j; }
            lkey = fkey(lmax);
        }
    }
    // gather phase: lanes 0..20 each own one group (8 candidates)
    const float* drow = d_dist + (long)row * Npt;
    float c[8];
    int base = 0;
    if (lane < KG) {
        base = (mygroup >> 4) * 128 + (mygroup & 15) * 4;
        float4 a = *(const float4*)&drow[base];
        float4 bb = *(const float4*)&drow[base + 64];
        c[0] = a.x;  c[1] = a.y;  c[2] = a.z;  c[3] = a.w;
        c[4] = bb.x; c[5] = bb.y; c[6] = bb.z; c[7] = bb.w;
    } else {
        #pragma unroll
        for (int j = 0; j < 8; j++) c[j] = -FLT_MAX;
    }
    float cmax = c[0]; int cj = 0;
    #pragma unroll
    for (int j = 1; j < 8; j++) if (c[j] > cmax) { cmax = c[j]; cj = j; }
    unsigned ckey = fkey(cmax);
    #pragma unroll 1
    for (int t = 0; t < KNN; t++) {
        unsigned lidx = (unsigned)(base + (cj < 4 ? cj : 60 + cj));
        unsigned wkey = __reduce_max_sync(0xffffffffu, ckey);
        unsigned bidx = __reduce_min_sync(0xffffffffu, (ckey == wkey) ? lidx : 0xffffffffu);
        if (lane == 0) d_idx[row * KNN + t] = (int)bidx;
        if (ckey == wkey && lidx == bidx) {
            #pragma unroll
            for (int j = 0; j < 8; j++) if (j == cj) c[j] = -FLT_MAX;
            cmax = c[0]; cj = 0;
            #pragma unroll
            for (int j = 1; j < 8; j++) if (c[j] > cmax) { cmax = c[j]; cj = j; }
            ckey = fkey(cmax);
        }
    }
}

// ======== 128x128 tile feature GEMM ========
__global__ void __launch_bounds__(256, 1) k_gemm128(
        float* __restrict__ out, const float* __restrict__ in,
        const float* __restrict__ W, const float* __restrict__ biasBO,
        int C, int ldw, int CTin, int c0in, int CTout, int c0out) {
    __shared__ float Ws[16][132];
    __shared__ float Xs[16][128];
    int b = blockIdx.z, o0 = blockIdx.y * 128, n0 = blockIdx.x * 128;
    int tid = threadIdx.x, tx = tid & 15, ty = tid >> 4;
    float acc[2][2][4][4] = {};
    const float* inB = in + ((long)b * CTin + c0in) * Npt + n0;
    #pragma unroll 1
    for (int ck = 0; ck < C; ck += 16) {
        #pragma unroll
        for (int r = 0; r < 8; r++) {
            int idx = r * 256 + tid;
            int oo = idx >> 4, cc = idx & 15;
            Ws[cc][oo] = W[(long)(o0 + oo) * ldw + ck + cc];
        }
        #pragma unroll
        for (int r = 0; r < 8; r++) {
            int idx = r * 256 + tid;
            int cc = idx >> 7, e = idx & 127;
            Xs[cc][e] = inB[(long)(ck + cc) * Npt + e];
        }
        __syncthreads();
        #pragma unroll
        for (int k = 0; k < 16; k++) {
            float4 a0 = *(const float4*)&Ws[k][ty * 4];
            float4 a1 = *(const float4*)&Ws[k][64 + ty * 4];
            float4 b0 = *(const float4*)&Xs[k][tx * 4];
            float4 b1 = *(const float4*)&Xs[k][64 + tx * 4];
            float aa[2][4] = {{a0.x, a0.y, a0.z, a0.w}, {a1.x, a1.y, a1.z, a1.w}};
            float bb[2][4] = {{b0.x, b0.y, b0.z, b0.w}, {b1.x, b1.y, b1.z, b1.w}};
            #pragma unroll
            for (int ii = 0; ii < 2; ii++)
                #pragma unroll
                for (int i = 0; i < 4; i++)
                    #pragma unroll
                    for (int jj = 0; jj < 2; jj++)
                        #pragma unroll
                        for (int j = 0; j < 4; j++)
                            acc[ii][jj][i][j] += aa[ii][i] * bb[jj][j];
        }
        __syncthreads();
    }
    #pragma unroll
    for (int ii = 0; ii < 2; ii++) {
        #pragma unroll
        for (int i = 0; i < 4; i++) {
            int o = o0 + ii * 64 + ty * 4 + i;
            float bias = biasBO ? biasBO[b * 512 + o] : 0.f;
            float* row = out + ((long)b * CTout + c0out + o) * Npt + n0;
            float4 v0, v1;
            v0.x = acc[ii][0][i][0] + bias; v0.y = acc[ii][0][i][1] + bias;
            v0.z = acc[ii][0][i][2] + bias; v0.w = acc[ii][0][i][3] + bias;
            v1.x = acc[ii][1][i][0] + bias; v1.y = acc[ii][1][i][1] + bias;
            v1.z = acc[ii][1][i][2] + bias; v1.w = acc[ii][1][i][3] + bias;
            *(float4*)&row[tx * 4] = v0;
            *(float4*)&row[64 + tx * 4] = v1;
        }
    }
}

// ======== edge-conv GEMM: output [A;C], weights transformed inline from W[128x128] ========
// rows 0:64 use W[o, 0:64]; rows 64:128 use W[o-64, 64:128] - W[o-64, 0:64]
__global__ void __launch_bounds__(256, 1) k_gemm_edge(
        float* __restrict__ out, const float* __restrict__ in,
        const float* __restrict__ W, int c0in) {
    __shared__ float Ws[16][132];
    __shared__ float Xs[16][128];
    int b = blockIdx.z, n0 = blockIdx.x * 128;
    int tid = threadIdx.x, tx = tid & 15, ty = tid >> 4;
    float acc[2][2][4][4] = {};
    const float* inB = in + ((long)b * 192 + c0in) * Npt + n0;
    #pragma unroll 1
    for (int ck = 0; ck < 64; ck += 16) {
        #pragma unroll
        for (int r = 0; r < 8; r++) {
            int idx = r * 256 + tid;
            int oo = idx >> 4, cc = idx & 15;
            float w;
            if (oo < 64) {
                w = W[oo * 128 + ck + cc];
            } else {
                int o2 = oo - 64;
                w = W[o2 * 128 + 64 + ck + cc] - W[o2 * 128 + ck + cc];
            }
            Ws[cc][oo] = w;
        }
        #pragma unroll
        for (int r = 0; r < 8; r++) {
            int idx = r * 256 + tid;
            int cc = idx >> 7, e = idx & 127;
            Xs[cc][e] = inB[(long)(ck + cc) * Npt + e];
        }
        __syncthreads();
        #pragma unroll
        for (int k = 0; k < 16; k++) {
            float4 a0 = *(const float4*)&Ws[k][ty * 4];
            float4 a1 = *(const float4*)&Ws[k][64 + ty * 4];
            float4 b0 = *(const float4*)&Xs[k][tx * 4];
            float4 b1 = *(const float4*)&Xs[k][64 + tx * 4];
            float aa[2][4] = {{a0.x, a0.y, a0.z, a0.w}, {a1.x, a1.y, a1.z, a1.w}};
            float bb[2][4] = {{b0.x, b0.y, b0.z, b0.w}, {b1.x, b1.y, b1.z, b1.w}};
            #pragma unroll
            for (int ii = 0; ii < 2; ii++)
                #pragma unroll
                for (int i = 0; i < 4; i++)
                    #pragma unroll
                    for (int jj = 0; jj < 2; jj++)
                        #pragma unroll
                        for (int j = 0; j < 4; j++)
                            acc[ii][jj][i][j] += aa[ii][i] * bb[jj][j];
        }
        __syncthreads();
    }
    #pragma unroll
    for (int ii = 0; ii < 2; ii++) {
        #pragma unroll
        for (int i = 0; i < 4; i++) {
            int o = ii * 64 + ty * 4 + i;
            float* row = out + ((long)b * 128 + o) * Npt + n0;
            float4 v0 = make_float4(acc[ii][0][i][0], acc[ii][0][i][1], acc[ii][0][i][2], acc[ii][0][i][3]);
            float4 v1 = make_float4(acc[ii][1][i][0], acc[ii][1][i][1], acc[ii][1][i][2], acc[ii][1][i][3]);
            *(float4*)&row[tx * 4] = v0;
            *(float4*)&row[64 + tx * 4] = v1;
        }
    }
}

// ---------------- edge-conv BN stats: stage 1 (64 channels x 8 slices) ----------------
__global__ void k_edge_stats_part() {
    int o = blockIdx.x, slice = blockIdx.y;
    int tid = threadIdx.x;
    float s = 0.f, sc = 0.f, s2 = 0.f, s2c = 0.f;
    #pragma unroll 1
    for (int b = 0; b < Bsz; b++) {
        const float* Ab = d_AC + ((long)b * 128 + o) * Npt;
        const float* Cb = d_AC + ((long)b * 128 + 64 + o) * Npt;
        #pragma unroll 1
        for (int n = slice * 512 + tid; n < (slice + 1) * 512; n += 256) {
            float cc = Cb[n];
            const int* ip = d_idx + ((long)(b * Npt + n)) * KNN;
            #pragma unroll 4
            for (int k = 0; k < KNN; k++) {
                float v = Ab[ip[k]] + cc;
                kadd(s, sc, v);
                kadd(s2, s2c, v * v);
            }
        }
    }
    __shared__ float sh[256], sh2[256];
    sh[tid] = s; sh2[tid] = s2; __syncthreads();
    for (int st = 128; st > 0; st >>= 1) {
        if (tid < st) { sh[tid] += sh[tid + st]; sh2[tid] += sh2[tid + st]; }
        __syncthreads();
    }
    if (tid == 0) {
        d_espart[(o * 8 + slice) * 2 + 0] = sh[0];
        d_espart[(o * 8 + slice) * 2 + 1] = sh2[0];
    }
}

// ---------------- edge-conv BN+lrelu+max_k (finalize folded in) ----------------
__global__ void k_edge_apply(const float* __restrict__ gamma, const float* __restrict__ beta, int c0out) {
    int n = blockIdx.x * 256 + threadIdx.x, o = blockIdx.y, b = blockIdx.z;
    float s = 0.f, s2 = 0.f;
    #pragma unroll
    for (int p = 0; p < 8; p++) {
        s += d_espart[(o * 8 + p) * 2 + 0];
        s2 += d_espart[(o * 8 + p) * 2 + 1];
    }
    float cnt = (float)(Bsz * Npt * KNN);
    float m = s / cnt;
    float var = s2 / cnt - m * m;
    float r = rsqrtf(fmaxf(var, 0.f) + EPSBN);
    float g = gamma[o], be = beta[o];
    const float* Ab = d_AC + ((long)b * 128 + o) * Npt;
    float cc = d_AC[((long)b * 128 + 64 + o) * Npt + n];
    const int* ip = d_idx + (b * Npt + n) * KNN;
    float best = -FLT_MAX;
    #pragma unroll 4
    for (int k = 0; k < KNN; k++) {
        float v = Ab[ip[k]] + cc;
        v = lrelu((v - m) * r * g + be);
        best = fmaxf(best, v);
    }
    d_xcat[((long)b * 192 + c0out + o) * Npt + n] = best;
}

// ---------------- fused stats + BN + lrelu + max over n -> gmax (fp32 Kahan) ----------------
__global__ void k_stats_gmax(const float* __restrict__ buf,
                             const float* __restrict__ gamma, const float* __restrict__ beta) {
    int o = blockIdx.x;  // 512
    float s = 0.f, sc = 0.f, s2 = 0.f, s2c = 0.f;
    for (int i = threadIdx.x; i < Bsz * Npt; i += 256) {
        int b = i >> 12, n = i & (Npt - 1);
        float v = buf[((long)b * 512 + o) * Npt + n];
        kadd(s, sc, v);
        kadd(s2, s2c, v * v);
    }
    __shared__ float sh[256], sh2[256];
    __shared__ float smv, srv;
    sh[threadIdx.x] = s; sh2[threadIdx.x] = s2; __syncthreads();
    for (int st = 128; st > 0; st >>= 1) {
        if (threadIdx.x < st) { sh[threadIdx.x] += sh[threadIdx.x + st]; sh2[threadIdx.x] += sh2[threadIdx.x + st]; }
        __syncthreads();
    }
    if (threadIdx.x == 0) {
        float cnt = (float)(Bsz * Npt);
        float m = sh[0] / cnt;
        float var = sh2[0] / cnt - m * m;
        smv = m;
        srv = rsqrtf(fmaxf(var, 0.f) + EPSBN);
    }
    __syncthreads();
    float m = smv, r = srv, g = gamma[o], be = beta[o];
    __shared__ float shm[256];
    for (int b = 0; b < Bsz; b++) {
        float best = -FLT_MAX;
        for (int n = threadIdx.x; n < Npt; n += 256) {
            float v = buf[((long)b * 512 + o) * Npt + n];
            best = fmaxf(best, lrelu((v - m) * r * g + be));
        }
        shm[threadIdx.x] = best; __syncthreads();
        for (int st = 128; st > 0; st >>= 1) {
            if (threadIdx.x < st) shm[threadIdx.x] = fmaxf(shm[threadIdx.x], shm[threadIdx.x + st]);
            __syncthreads();
        }
        if (threadIdx.x == 0) d_gmax[b * 512 + o] = shm[0];
        __syncthreads();
    }
}

// ---------------- fold W5[:,192:] @ broadcast(gmax) into a per-(b,o) bias ----------------
__global__ void k_bias5(const float* __restrict__ W5) {
    int t = blockIdx.x * 128 + threadIdx.x;
    int b = t >> 9, o = t & 511;
    float s = 0.f;
    #pragma unroll 8
    for (int c = 0; c < 512; c++)
        s += W5[(long)o * 704 + 192 + c] * d_gmax[b * 512 + c];
    d_bias5[b * 512 + o] = s;
}

// ---------------- final conv 128 -> 2 + bias ----------------
__global__ void k_final(const float* __restrict__ W8, const float* __restrict__ b8,
                        float* __restrict__ out) {
    int n = blockIdx.x * 256 + threadIdx.x, b = blockIdx.y;
    float s0 = b8[0], s1 = b8[1];
    #pragma unroll 8
    for (int c = 0; c < 128; c++) {
        float h = d_y7[((long)b * 128 + c) * Npt + n];
        s0 += W8[c] * h;
        s1 += W8[128 + c] * h;
    }
    out[(b * 2 + 0) * Npt + n] = s0;
    out[(b * 2 + 1) * Npt + n] = s1;
}

// ---------------- host ----------------
extern "C" void kernel_launch(void* const* d_in, const int* in_sizes, int n_in,
                              void* d_out, int out_size) {
    (void)in_sizes; (void)n_in; (void)out_size;
    const float* x   = (const float*)d_in[0];
    const float* W1  = (const float*)d_in[1];
    const float* W2  = (const float*)d_in[2];
    const float* W3  = (const float*)d_in[3];
    const float* W4  = (const float*)d_in[4];
    const float* W5  = (const float*)d_in[5];
    const float* W6  = (const float*)d_in[6];
    const float* W7  = (const float*)d_in[7];
    const float* W8  = (const float*)d_in[8];
    const float* b8  = (const float*)d_in[9];
    const float* g1 = (const float*)d_in[10], *bb1 = (const float*)d_in[11];
    const float* g2 = (const float*)d_in[12], *bb2 = (const float*)d_in[13];
    const float* g3 = (const float*)d_in[14], *bb3 = (const float*)d_in[15];
    const float* g4 = (const float*)d_in[16], *bb4 = (const float*)d_in[17];
    const float* g5 = (const float*)d_in[18], *bb5 = (const float*)d_in[19];
    const float* g6 = (const float*)d_in[20], *bb6 = (const float*)d_in[21];
    const float* g7 = (const float*)d_in[22], *bb7 = (const float*)d_in[23];

    void *pv;
    cudaGetSymbolAddress(&pv, d_xcat);  float* p_xcat = (float*)pv;
    cudaGetSymbolAddress(&pv, d_AC);    float* p_AC   = (float*)pv;
    cudaGetSymbolAddress(&pv, d_y4);    float* p_y4   = (float*)pv;
    cudaGetSymbolAddress(&pv, d_y5);    float* p_y5   = (float*)pv;
    cudaGetSymbolAddress(&pv, d_y6);    float* p_y6   = (float*)pv;
    cudaGetSymbolAddress(&pv, d_y7);    float* p_y7   = (float*)pv;
    cudaGetSymbolAddress(&pv, d_bias5); float* p_b5   = (float*)pv;

    // conv1 + BN + lrelu -> x1 (xcat[0:64))
    k_conv1<<<dim3(16, 64, 4), 256>>>(x, W1);
    k_statsapply<<<64, 256>>>(p_xcat, 192, 0, g1, bb1);

    // kNN round 1 on x1: symmetric dist + group max -> fused select
    k_dist_sym<<<dim3(32, 32, 4), 256>>>(0);
    k_knn_select<<<2048, 256>>>();

    // edge-conv 2 -> x2 (xcat[64:128))
    k_gemm_edge<<<dim3(32, 1, 4), 256>>>(p_AC, p_xcat, W2, 0);
    k_edge_stats_part<<<dim3(64, 8), 256>>>();
    k_edge_apply<<<dim3(16, 64, 4), 256>>>(g2, bb2, 64);

    // kNN round 2 on x2
    k_dist_sym<<<dim3(32, 32, 4), 256>>>(64);
    k_knn_select<<<2048, 256>>>();

    // edge-conv 3 -> x3 (xcat[128:192))
    k_gemm_edge<<<dim3(32, 1, 4), 256>>>(p_AC, p_xcat, W3, 64);
    k_edge_stats_part<<<dim3(64, 8), 256>>>();
    k_edge_apply<<<dim3(16, 64, 4), 256>>>(g3, bb3, 128);

    // global branch: y4 = W4 @ x3; fused stats+BN+lrelu+max -> gmax; fold into bias5
    k_gemm128<<<dim3(32, 4, 4), 256>>>(p_y4, p_xcat, W4, nullptr, 64, 64, 192, 128, 512, 0);
    k_stats_gmax<<<512, 256>>>(p_y4, g4, bb4);
    k_bias5<<<16, 128>>>(W5);

    // W5 on [x1;x2;x3] (C=192) + bias5; BN; lrelu
    k_gemm128<<<dim3(32, 4, 4), 256>>>(p_y5, p_xcat, W5, p_b5, 192, 704, 192, 0, 512, 0);
    k_statsapply<<<512, 256>>>(p_y5, 512, 0, g5, bb5);

    // W6
    k_gemm128<<<dim3(32, 2, 4), 256>>>(p_y6, p_y5, W6, nullptr, 512, 512, 512, 0, 256, 0);
    k_statsapply<<<256, 256>>>(p_y6, 256, 0, g6, bb6);

    // W7
    k_gemm128<<<dim3(32, 1, 4), 256>>>(p_y7, p_y6, W7, nullptr, 256, 256, 256, 0, 128, 0);
    k_statsapply<<<128, 256>>>(p_y7, 128, 0, g7, bb7);

    // final 128 -> 2
    k_final<<<dim3(16, 4), 256>>>(W8, b8, (float*)d_out);
}